// round 8
// baseline (speedup 1.0000x reference)
#include <cuda_runtime.h>
#include <cuda_bf16.h>
#include <cstdint>

#define BB   2
#define TT   2048
#define CC   1024
#define HH   16
#define DD   64
#define C3   3072
#define MM   (BB * TT)        // 4096

// ---------------- scratch (static device globals; no allocations) -------------
__device__ float g_qkv[BB * TT * C3];              // [B,T,3C] fp32

__device__ __nv_bfloat16 g_xhi[MM * CC];           // x split  [M,K]
__device__ __nv_bfloat16 g_xlo[MM * CC];
__device__ __nv_bfloat16 g_wqhi[C3 * CC];          // Wqkv^T split [N,K]
__device__ __nv_bfloat16 g_wqlo[C3 * CC];
__device__ __nv_bfloat16 g_wphi[CC * CC];          // Wproj^T split [N,K]
__device__ __nv_bfloat16 g_wplo[CC * CC];
__device__ __nv_bfloat16 g_yhi[MM * CC];           // attention out split [B,T,C]
__device__ __nv_bfloat16 g_ylo[MM * CC];

// Q/K/V bf16 hi/lo in [B,H,T,D] (Q pre-scaled by 1/8)
__device__ __nv_bfloat16 g_qh[MM * CC];
__device__ __nv_bfloat16 g_ql[MM * CC];
__device__ __nv_bfloat16 g_kh[MM * CC];
__device__ __nv_bfloat16 g_kl[MM * CC];
__device__ __nv_bfloat16 g_vh[MM * CC];
__device__ __nv_bfloat16 g_vl[MM * CC];

// ---------------- helpers ------------------------------------------------------
__device__ __forceinline__ uint32_t smem_u32(const void* p) {
    uint32_t a;
    asm("{ .reg .u64 t; cvta.to.shared.u64 t, %1; cvt.u32.u64 %0, t; }"
        : "=r"(a) : "l"(p));
    return a;
}

__device__ __forceinline__ void ldsm_x4(uint32_t r[4], uint32_t addr) {
    asm volatile("ldmatrix.sync.aligned.m8n8.x4.shared.b16 {%0,%1,%2,%3}, [%4];"
                 : "=r"(r[0]), "=r"(r[1]), "=r"(r[2]), "=r"(r[3]) : "r"(addr));
}

__device__ __forceinline__ void ldsm_x4_t(uint32_t r[4], uint32_t addr) {
    asm volatile("ldmatrix.sync.aligned.m8n8.x4.trans.shared.b16 {%0,%1,%2,%3}, [%4];"
                 : "=r"(r[0]), "=r"(r[1]), "=r"(r[2]), "=r"(r[3]) : "r"(addr));
}

__device__ __forceinline__ void mma_bf16(float d[4], const uint32_t a[4],
                                         const uint32_t b[2]) {
    asm volatile(
        "mma.sync.aligned.m16n8k16.row.col.f32.bf16.bf16.f32 "
        "{%0,%1,%2,%3}, {%4,%5,%6,%7}, {%8,%9}, {%0,%1,%2,%3};"
        : "+f"(d[0]), "+f"(d[1]), "+f"(d[2]), "+f"(d[3])
        : "r"(a[0]), "r"(a[1]), "r"(a[2]), "r"(a[3]), "r"(b[0]), "r"(b[1]));
}

__device__ __forceinline__ void cp_async16(uint32_t saddr, const void* gaddr) {
    asm volatile("cp.async.cg.shared.global [%0], [%1], 16;"
                 :: "r"(saddr), "l"(gaddr));
}
#define CP_COMMIT() asm volatile("cp.async.commit_group;" ::: "memory")
template <int N>
__device__ __forceinline__ void cp_wait() {
    asm volatile("cp.async.wait_group %0;" :: "n"(N) : "memory");
}

// split two floats into packed bf16x2 hi + lo(residual)
__device__ __forceinline__ void split2(float a, float b, uint32_t& hi, uint32_t& lo) {
    __nv_bfloat162 h = __floats2bfloat162_rn(a, b);
    hi = *(uint32_t*)&h;
    float ra = a - __bfloat162float(h.x);
    float rb = b - __bfloat162float(h.y);
    __nv_bfloat162 l2 = __floats2bfloat162_rn(ra, rb);
    lo = *(uint32_t*)&l2;
}

// ---------------- pre-pass: fp32 -> bf16 hi/lo split --------------------------
__global__ void split_kernel(const float* __restrict__ A,
                             __nv_bfloat16* __restrict__ hi,
                             __nv_bfloat16* __restrict__ lo, int n)
{
    int i = blockIdx.x * 256 + threadIdx.x;
    if (i < n) {
        float v = A[i];
        __nv_bfloat16 h = __float2bfloat16(v);
        hi[i] = h;
        lo[i] = __float2bfloat16(v - __bfloat162float(h));
    }
}

// transpose + split: W [K,N] fp32 -> hi/lo [N,K] bf16
__global__ void tsplit_kernel(const float* __restrict__ W,
                              __nv_bfloat16* __restrict__ hi,
                              __nv_bfloat16* __restrict__ lo, int K, int N)
{
    __shared__ float t[32][33];
    int k0 = blockIdx.y * 32, n0 = blockIdx.x * 32;
    int tx = threadIdx.x, ty = threadIdx.y;   // block (32,8)
#pragma unroll
    for (int i = 0; i < 32; i += 8)
        t[ty + i][tx] = W[(size_t)(k0 + ty + i) * N + n0 + tx];
    __syncthreads();
#pragma unroll
    for (int i = 0; i < 32; i += 8) {
        float v = t[tx][ty + i];
        size_t o = (size_t)(n0 + ty + i) * K + k0 + tx;
        __nv_bfloat16 h = __float2bfloat16(v);
        hi[o] = h;
        lo[o] = __float2bfloat16(v - __bfloat162float(h));
    }
}

// ---------------- mma.sync bf16 split GEMM (cp.async double-buffered) ---------
// C[M,N] = A[M,K] @ Bt[N,K]^T + bias, fp32 accum.
// CTA tile 128x64, BK=64, 8 warps (4m x 2n), warp tile 32x32.
#define GBM 128
#define GBN 64
#define GBK 64
#define KPAD 72                              // bf16 elems per smem row (144 B)
#define AHO  0
#define ALO_ 18432
#define BHO  36864
#define BLO_ 46080
#define STG  55296
#define GSMEM (2 * STG)                      // 110592 B

__global__ void __launch_bounds__(256)
gemm_mma_kernel(const __nv_bfloat16* __restrict__ Ahi,
                const __nv_bfloat16* __restrict__ Alo,
                const __nv_bfloat16* __restrict__ Bhi,
                const __nv_bfloat16* __restrict__ Blo,
                const float* __restrict__ bias,
                float* __restrict__ Cm,
                int N, int K)
{
    extern __shared__ __align__(16) unsigned char smem[];
    const uint32_t sb = smem_u32(smem);

    const int tid  = threadIdx.x;
    const int lane = tid & 31;
    const int w    = tid >> 5;
    const int m_base = (w & 3) * 32;
    const int n_base = (w >> 2) * 32;

    const int m0 = blockIdx.y * GBM;
    const int n0 = blockIdx.x * GBN;

    // per-thread load coordinates
    const int l_row = tid >> 3;              // 0..31
    const int l_c8  = (tid & 7) * 8;         // bf16 col
    const uint32_t l_soff = (uint32_t)(l_row * KPAD + l_c8) * 2;

    auto load_chunk = [&](int buf, int k0) {
        uint32_t base = sb + buf * STG;
#pragma unroll
        for (int it = 0; it < 4; it++) {
            int row = l_row + it * 32;
            size_t g = (size_t)(m0 + row) * K + k0 + l_c8;
            uint32_t s = base + l_soff + (uint32_t)(it * 32 * KPAD * 2);
            cp_async16(s + AHO,  Ahi + g);
            cp_async16(s + ALO_, Alo + g);
        }
#pragma unroll
        for (int it = 0; it < 2; it++) {
            int row = l_row + it * 32;
            size_t g = (size_t)(n0 + row) * K + k0 + l_c8;
            uint32_t s = base + l_soff + (uint32_t)(it * 32 * KPAD * 2);
            cp_async16(s + BHO,  Bhi + g);
            cp_async16(s + BLO_, Blo + g);
        }
    };

    float d[2][4][4];
#pragma unroll
    for (int i = 0; i < 2; i++)
#pragma unroll
        for (int j = 0; j < 4; j++)
#pragma unroll
            for (int r = 0; r < 4; r++) d[i][j][r] = 0.f;

    const int a_m   = m_base + (lane & 7) + ((lane >> 3) & 1) * 8;
    const int a_khi = (lane >> 4) * 8;
    const int b_g   = lane >> 3;
    const int b_n8  = (b_g >> 1) * 8 + (lane & 7);
    const int b_k8  = (b_g & 1) * 8;

    const int NC = K / GBK;
    load_chunk(0, 0);
    CP_COMMIT();

    for (int c = 0; c < NC; c++) {
        if (c + 1 < NC) {
            load_chunk((c + 1) & 1, (c + 1) * GBK);
            CP_COMMIT();
            cp_wait<1>();
        } else {
            cp_wait<0>();
        }
        __syncthreads();

        const uint32_t st = sb + (c & 1) * STG;
#pragma unroll
        for (int ks = 0; ks < 4; ks++) {
            const int koff = ks * 16;
            uint32_t ah[2][4], al[2][4], bh[4][2], bl[4][2];
#pragma unroll
            for (int mf = 0; mf < 2; mf++) {
                uint32_t off = (uint32_t)((a_m + mf * 16) * KPAD + koff + a_khi) * 2;
                ldsm_x4(ah[mf], st + AHO + off);
                ldsm_x4(al[mf], st + ALO_ + off);
            }
#pragma unroll
            for (int pr = 0; pr < 2; pr++) {
                uint32_t off = (uint32_t)((n_base + pr * 16 + b_n8) * KPAD + koff + b_k8) * 2;
                uint32_t rh[4], rl[4];
                ldsm_x4(rh, st + BHO + off);
                ldsm_x4(rl, st + BLO_ + off);
                bh[pr * 2 + 0][0] = rh[0]; bh[pr * 2 + 0][1] = rh[1];
                bh[pr * 2 + 1][0] = rh[2]; bh[pr * 2 + 1][1] = rh[3];
                bl[pr * 2 + 0][0] = rl[0]; bl[pr * 2 + 0][1] = rl[1];
                bl[pr * 2 + 1][0] = rl[2]; bl[pr * 2 + 1][1] = rl[3];
            }
#pragma unroll
            for (int mf = 0; mf < 2; mf++)
#pragma unroll
                for (int nf = 0; nf < 4; nf++) {
                    mma_bf16(d[mf][nf], ah[mf], bh[nf]);
                    mma_bf16(d[mf][nf], ah[mf], bl[nf]);
                    mma_bf16(d[mf][nf], al[mf], bh[nf]);
                }
        }
        __syncthreads();
    }

#pragma unroll
    for (int mf = 0; mf < 2; mf++) {
#pragma unroll
        for (int nf = 0; nf < 4; nf++) {
            int row = m0 + m_base + mf * 16 + (lane >> 2);
            int col = n0 + n_base + nf * 8 + 2 * (lane & 3);
            float bx = bias[col], by = bias[col + 1];
            float2 v0 = {d[mf][nf][0] + bx, d[mf][nf][1] + by};
            float2 v1 = {d[mf][nf][2] + bx, d[mf][nf][3] + by};
            *(float2*)&Cm[(size_t)row * N + col]       = v0;
            *(float2*)&Cm[(size_t)(row + 8) * N + col] = v1;
        }
    }
}

// ---------------- RoPE + scatter + bf16 hi/lo split ---------------------------
__global__ void rope_split_kernel(const float* __restrict__ qkv,
                                  const float* __restrict__ cosT,
                                  const float* __restrict__ sinT)
{
    int idx = blockIdx.x * blockDim.x + threadIdx.x;
    const int total = BB * HH * TT * (DD / 2);
    if (idx >= total) return;

    int i  = idx & 31;
    int t  = (idx >> 5) & (TT - 1);
    int hh = (idx >> 5) / TT;
    int h  = hh & (HH - 1);
    int b  = hh >> 4;

    float c = cosT[t * 32 + i];
    float s = sinT[t * 32 + i];

    const float* base = qkv + (size_t)(b * TT + t) * C3 + h * DD;
    size_t oBase = ((size_t)(b * HH + h) * TT + t) * DD + 2 * i;

    uint32_t hi, lo;
    float q1 = base[2 * i], q2 = base[2 * i + 1];
    split2((q1 * c - q2 * s) * 0.125f, (q1 * s + q2 * c) * 0.125f, hi, lo);
    *(uint32_t*)&g_qh[oBase] = hi;
    *(uint32_t*)&g_ql[oBase] = lo;

    float k1 = base[CC + 2 * i], k2 = base[CC + 2 * i + 1];
    split2(k1 * c - k2 * s, k1 * s + k2 * c, hi, lo);
    *(uint32_t*)&g_kh[oBase] = hi;
    *(uint32_t*)&g_kl[oBase] = lo;

    split2(base[2 * CC + 2 * i], base[2 * CC + 2 * i + 1], hi, lo);
    *(uint32_t*)&g_vh[oBase] = hi;
    *(uint32_t*)&g_vl[oBase] = lo;
}

// ---------------- tensor-core causal flash attention (cp.async pipelined) -----
// BQ=128, BKV=64, 8 warps x 16 q-rows. Q frags loaded global->register.
#define FKP 72
#define FKH 0
#define FKL 9216
#define FVH 18432
#define FVL 27648
#define FS  36864
#define FLASH_SMEM (2 * FS)    // 73728

__global__ void __launch_bounds__(256)
flash_mma_kernel(const __nv_bfloat16* __restrict__ Qh,
                 const __nv_bfloat16* __restrict__ Ql,
                 const __nv_bfloat16* __restrict__ Kh,
                 const __nv_bfloat16* __restrict__ Kl,
                 const __nv_bfloat16* __restrict__ Vh,
                 const __nv_bfloat16* __restrict__ Vl)
{
    extern __shared__ __align__(16) unsigned char smem[];
    const uint32_t sb = smem_u32(smem);
    const int tid  = threadIdx.x;
    const int lane = tid & 31;
    const int w    = tid >> 5;

    const int qt = gridDim.x - 1 - blockIdx.x;   // heavy tiles first
    const int q0 = qt * 128;
    const int bh = blockIdx.y;
    const size_t gbase = (size_t)bh * TT * DD;

    // ---- Q fragments directly from global (mma A-frag coordinates) ----
    const int fr = lane >> 2;                 // 0..7
    const int fc = (lane & 3) * 2;            // 0,2,4,6
    const size_t qrow0 = gbase + (size_t)(q0 + w * 16 + fr) * DD;
    const size_t qrow1 = qrow0 + 8 * DD;
    uint32_t qh[4][4], ql[4][4];
#pragma unroll
    for (int ks = 0; ks < 4; ks++) {
        int cA = ks * 16 + fc;
        qh[ks][0] = *(const uint32_t*)&Qh[qrow0 + cA];
        qh[ks][1] = *(const uint32_t*)&Qh[qrow1 + cA];
        qh[ks][2] = *(const uint32_t*)&Qh[qrow0 + cA + 8];
        qh[ks][3] = *(const uint32_t*)&Qh[qrow1 + cA + 8];
        ql[ks][0] = *(const uint32_t*)&Ql[qrow0 + cA];
        ql[ks][1] = *(const uint32_t*)&Ql[qrow1 + cA];
        ql[ks][2] = *(const uint32_t*)&Ql[qrow0 + cA + 8];
        ql[ks][3] = *(const uint32_t*)&Ql[qrow1 + cA + 8];
    }

    // per-thread KV load coordinates
    const int l_row = tid >> 3;
    const int l_c8  = (tid & 7) * 8;
    const uint32_t l_soff = (uint32_t)(l_row * FKP + l_c8) * 2;

    auto load_kv = [&](int buf, int kv0) {
        uint32_t base = sb + buf * FS;
#pragma unroll
        for (int it = 0; it < 2; it++) {
            int row = l_row + it * 32;
            size_t g = gbase + (size_t)(kv0 + row) * DD + l_c8;
            uint32_t s = base + l_soff + (uint32_t)(it * 32 * FKP * 2);
            cp_async16(s + FKH, Kh + g);
            cp_async16(s + FKL, Kl + g);
            cp_async16(s + FVH, Vh + g);
            cp_async16(s + FVL, Vl + g);
        }
    };

    const int b_g   = lane >> 3;
    const int b_n8  = (b_g >> 1) * 8 + (lane & 7);
    const int b_k8  = (b_g & 1) * 8;
    const int v_r8  = (b_g & 1) * 8 + (lane & 7);
    const int v_c8  = (b_g >> 1) * 8;

    float o[8][4];
#pragma unroll
    for (int nf = 0; nf < 8; nf++)
#pragma unroll
        for (int j = 0; j < 4; j++) o[nf][j] = 0.f;
    float m0 = -1e30f, m1 = -1e30f, l0 = 0.f, l1 = 0.f;

    const int r0g = q0 + w * 16 + fr;
    const int nchunk = 2 * qt + 2;

    load_kv(0, 0);
    CP_COMMIT();

    for (int ch = 0; ch < nchunk; ch++) {
        const int kv0 = ch * 64;
        if (ch + 1 < nchunk) {
            load_kv((ch + 1) & 1, (ch + 1) * 64);
            CP_COMMIT();
            cp_wait<1>();
        } else {
            cp_wait<0>();
        }
        __syncthreads();
        const uint32_t st = sb + (ch & 1) * FS;

        // ---- S = Q K^T (3-term split) ----
        float s4[8][4];
#pragma unroll
        for (int nf = 0; nf < 8; nf++)
#pragma unroll
            for (int j = 0; j < 4; j++) s4[nf][j] = 0.f;

#pragma unroll
        for (int ks = 0; ks < 4; ks++) {
#pragma unroll
            for (int pr = 0; pr < 4; pr++) {
                uint32_t off = (uint32_t)((pr * 16 + b_n8) * FKP + ks * 16 + b_k8) * 2;
                uint32_t kh4[4], kl4[4];
                ldsm_x4(kh4, st + FKH + off);
                ldsm_x4(kl4, st + FKL + off);
                uint32_t bh0[2] = {kh4[0], kh4[1]}, bh1[2] = {kh4[2], kh4[3]};
                uint32_t bl0[2] = {kl4[0], kl4[1]}, bl1[2] = {kl4[2], kl4[3]};
                mma_bf16(s4[2 * pr], qh[ks], bh0);
                mma_bf16(s4[2 * pr], qh[ks], bl0);
                mma_bf16(s4[2 * pr], ql[ks], bh0);
                mma_bf16(s4[2 * pr + 1], qh[ks], bh1);
                mma_bf16(s4[2 * pr + 1], qh[ks], bl1);
                mma_bf16(s4[2 * pr + 1], ql[ks], bh1);
            }
        }

        // ---- causal mask (only last two chunks of this tile) ----
        if (ch >= 2 * qt) {
#pragma unroll
            for (int nf = 0; nf < 8; nf++) {
                int cbase = kv0 + nf * 8 + (lane & 3) * 2;
#pragma unroll
                for (int j = 0; j < 4; j++) {
                    int col = cbase + (j & 1);
                    int row = r0g + ((j >> 1) << 3);
                    if (col > row) s4[nf][j] = -1e30f;
                }
            }
        }

        // ---- online softmax ----
        float mx0 = -1e30f, mx1 = -1e30f;
#pragma unroll
        for (int nf = 0; nf < 8; nf++) {
            mx0 = fmaxf(mx0, fmaxf(s4[nf][0], s4[nf][1]));
            mx1 = fmaxf(mx1, fmaxf(s4[nf][2], s4[nf][3]));
        }
        mx0 = fmaxf(mx0, __shfl_xor_sync(0xffffffffu, mx0, 1));
        mx0 = fmaxf(mx0, __shfl_xor_sync(0xffffffffu, mx0, 2));
        mx1 = fmaxf(mx1, __shfl_xor_sync(0xffffffffu, mx1, 1));
        mx1 = fmaxf(mx1, __shfl_xor_sync(0xffffffffu, mx1, 2));
        float mn0 = fmaxf(m0, mx0), mn1 = fmaxf(m1, mx1);
        float al0 = __expf(m0 - mn0), al1 = __expf(m1 - mn1);
        float sum0 = 0.f, sum1 = 0.f;
#pragma unroll
        for (int nf = 0; nf < 8; nf++) {
            s4[nf][0] = __expf(s4[nf][0] - mn0);
            s4[nf][1] = __expf(s4[nf][1] - mn0);
            s4[nf][2] = __expf(s4[nf][2] - mn1);
            s4[nf][3] = __expf(s4[nf][3] - mn1);
            sum0 += s4[nf][0] + s4[nf][1];
            sum1 += s4[nf][2] + s4[nf][3];
        }
        sum0 += __shfl_xor_sync(0xffffffffu, sum0, 1);
        sum0 += __shfl_xor_sync(0xffffffffu, sum0, 2);
        sum1 += __shfl_xor_sync(0xffffffffu, sum1, 1);
        sum1 += __shfl_xor_sync(0xffffffffu, sum1, 2);
        l0 = l0 * al0 + sum0;  m0 = mn0;
        l1 = l1 * al1 + sum1;  m1 = mn1;
#pragma unroll
        for (int nf = 0; nf < 8; nf++) {
            o[nf][0] *= al0; o[nf][1] *= al0;
            o[nf][2] *= al1; o[nf][3] *= al1;
        }

        // ---- O += P V (3-term split, P from registers) ----
#pragma unroll
        for (int ks = 0; ks < 4; ks++) {
            uint32_t pa_h[4], pa_l[4];
            split2(s4[2 * ks][0],     s4[2 * ks][1],     pa_h[0], pa_l[0]);
            split2(s4[2 * ks][2],     s4[2 * ks][3],     pa_h[1], pa_l[1]);
            split2(s4[2 * ks + 1][0], s4[2 * ks + 1][1], pa_h[2], pa_l[2]);
            split2(s4[2 * ks + 1][2], s4[2 * ks + 1][3], pa_h[3], pa_l[3]);
#pragma unroll
            for (int pr = 0; pr < 4; pr++) {
                uint32_t off = (uint32_t)((ks * 16 + v_r8) * FKP + pr * 16 + v_c8) * 2;
                uint32_t vh4[4], vl4[4];
                ldsm_x4_t(vh4, st + FVH + off);
                ldsm_x4_t(vl4, st + FVL + off);
                uint32_t bh0[2] = {vh4[0], vh4[1]}, bh1[2] = {vh4[2], vh4[3]};
                uint32_t bl0[2] = {vl4[0], vl4[1]}, bl1[2] = {vl4[2], vl4[3]};
                mma_bf16(o[2 * pr], pa_h, bh0);
                mma_bf16(o[2 * pr], pa_h, bl0);
                mma_bf16(o[2 * pr], pa_l, bh0);
                mma_bf16(o[2 * pr + 1], pa_h, bh1);
                mma_bf16(o[2 * pr + 1], pa_h, bl1);
                mma_bf16(o[2 * pr + 1], pa_l, bh1);
            }
        }
        __syncthreads();
    }

    // ---- epilogue: O /= l, write bf16 hi/lo to [B,T,C] ----
    float inv0 = 1.f / l0, inv1 = 1.f / l1;
    int b = bh >> 4, h = bh & 15;
    size_t base0 = ((size_t)(b * TT + r0g)) * CC + h * DD;
    size_t base1 = ((size_t)(b * TT + r0g + 8)) * CC + h * DD;
#pragma unroll
    for (int nf = 0; nf < 8; nf++) {
        int c = nf * 8 + (lane & 3) * 2;
        uint32_t hi, lo;
        split2(o[nf][0] * inv0, o[nf][1] * inv0, hi, lo);
        *(uint32_t*)&g_yhi[base0 + c] = hi;
        *(uint32_t*)&g_ylo[base0 + c] = lo;
        split2(o[nf][2] * inv1, o[nf][3] * inv1, hi, lo);
        *(uint32_t*)&g_yhi[base1 + c] = hi;
        *(uint32_t*)&g_ylo[base1 + c] = lo;
    }
}

// ---------------- launcher ----------------------------------------------------
extern "C" void kernel_launch(void* const* d_in, const int* in_sizes, int n_in,
                              void* d_out, int out_size)
{
    const float* x     = (const float*)d_in[0];
    const float* Wqkv  = (const float*)d_in[1];
    const float* bqkv  = (const float*)d_in[2];
    const float* Wproj = (const float*)d_in[3];
    const float* bproj = (const float*)d_in[4];
    const float* cosT  = (const float*)d_in[5];
    const float* sinT  = (const float*)d_in[6];
    float* out = (float*)d_out;

    float* qkv;
    __nv_bfloat16 *xhi, *xlo, *wqhi, *wqlo, *wphi, *wplo, *yhi, *ylo;
    __nv_bfloat16 *qh, *ql, *kh, *kl, *vh, *vl;
    cudaGetSymbolAddress((void**)&qkv,  g_qkv);
    cudaGetSymbolAddress((void**)&xhi,  g_xhi);
    cudaGetSymbolAddress((void**)&xlo,  g_xlo);
    cudaGetSymbolAddress((void**)&wqhi, g_wqhi);
    cudaGetSymbolAddress((void**)&wqlo, g_wqlo);
    cudaGetSymbolAddress((void**)&wphi, g_wphi);
    cudaGetSymbolAddress((void**)&wplo, g_wplo);
    cudaGetSymbolAddress((void**)&yhi,  g_yhi);
    cudaGetSymbolAddress((void**)&ylo,  g_ylo);
    cudaGetSymbolAddress((void**)&qh,   g_qh);
    cudaGetSymbolAddress((void**)&ql,   g_ql);
    cudaGetSymbolAddress((void**)&kh,   g_kh);
    cudaGetSymbolAddress((void**)&kl,   g_kl);
    cudaGetSymbolAddress((void**)&vh,   g_vh);
    cudaGetSymbolAddress((void**)&vl,   g_vl);

    static bool attr_set = false;
    if (!attr_set) {
        cudaFuncSetAttribute(gemm_mma_kernel,
                             cudaFuncAttributeMaxDynamicSharedMemorySize, GSMEM);
        cudaFuncSetAttribute(flash_mma_kernel,
                             cudaFuncAttributeMaxDynamicSharedMemorySize, FLASH_SMEM);
        attr_set = true;
    }

    // pre-pass: split x; transpose+split weights
    split_kernel<<<(MM * CC + 255) / 256, 256>>>(x, xhi, xlo, MM * CC);
    tsplit_kernel<<<dim3(C3 / 32, CC / 32), dim3(32, 8)>>>(Wqkv, wqhi, wqlo, CC, C3);
    tsplit_kernel<<<dim3(CC / 32, CC / 32), dim3(32, 8)>>>(Wproj, wphi, wplo, CC, CC);

    // 1) QKV projection (tensor cores, pipelined)
    gemm_mma_kernel<<<dim3(C3 / GBN, MM / GBM), 256, GSMEM>>>(
        xhi, xlo, wqhi, wqlo, bqkv, qkv, C3, CC);

    // 2) RoPE + scatter + bf16 split (Q pre-scaled by 1/8)
    {
        int total = BB * HH * TT * (DD / 2);
        rope_split_kernel<<<(total + 255) / 256, 256>>>(qkv, cosT, sinT);
    }

    // 3) tensor-core causal flash attention (pipelined)
    flash_mma_kernel<<<dim3(TT / 128, BB * HH), 256, FLASH_SMEM>>>(
        qh, ql, kh, kl, vh, vl);

    // 4) output projection (tensor cores, pipelined)
    gemm_mma_kernel<<<dim3(CC / GBN, MM / GBM), 256, GSMEM>>>(
        yhi, ylo, wphi, wplo, bproj, out, CC, CC);
}

// round 9
// speedup vs baseline: 1.4307x; 1.4307x over previous
#include <cuda_runtime.h>
#include <cuda_bf16.h>
#include <cstdint>

#define BB   2
#define TT   2048
#define CC   1024
#define HH   16
#define DD   64
#define C3   3072
#define MM   (BB * TT)        // 4096

// ---------------- scratch (static device globals; no allocations) -------------
__device__ __nv_bfloat16 g_wqhi[C3 * CC];          // Wqkv^T split [N,K]
__device__ __nv_bfloat16 g_wqlo[C3 * CC];
__device__ __nv_bfloat16 g_wphi[CC * CC];          // Wproj^T split [N,K]
__device__ __nv_bfloat16 g_wplo[CC * CC];
__device__ __nv_bfloat16 g_yhi[MM * CC];           // attention out split [B,T,C]
__device__ __nv_bfloat16 g_ylo[MM * CC];

// Q/K/V bf16 hi/lo in [B,H,T,D] (Q pre-scaled by 1/8)
__device__ __nv_bfloat16 g_qh[MM * CC];
__device__ __nv_bfloat16 g_ql[MM * CC];
__device__ __nv_bfloat16 g_kh[MM * CC];
__device__ __nv_bfloat16 g_kl[MM * CC];
__device__ __nv_bfloat16 g_vh[MM * CC];
__device__ __nv_bfloat16 g_vl[MM * CC];

// ---------------- helpers ------------------------------------------------------
__device__ __forceinline__ uint32_t smem_u32(const void* p) {
    uint32_t a;
    asm("{ .reg .u64 t; cvta.to.shared.u64 t, %1; cvt.u32.u64 %0, t; }"
        : "=r"(a) : "l"(p));
    return a;
}

__device__ __forceinline__ void ldsm_x4(uint32_t r[4], uint32_t addr) {
    asm volatile("ldmatrix.sync.aligned.m8n8.x4.shared.b16 {%0,%1,%2,%3}, [%4];"
                 : "=r"(r[0]), "=r"(r[1]), "=r"(r[2]), "=r"(r[3]) : "r"(addr));
}

__device__ __forceinline__ void ldsm_x4_t(uint32_t r[4], uint32_t addr) {
    asm volatile("ldmatrix.sync.aligned.m8n8.x4.trans.shared.b16 {%0,%1,%2,%3}, [%4];"
                 : "=r"(r[0]), "=r"(r[1]), "=r"(r[2]), "=r"(r[3]) : "r"(addr));
}

__device__ __forceinline__ void mma_bf16(float d[4], const uint32_t a[4],
                                         const uint32_t b[2]) {
    asm volatile(
        "mma.sync.aligned.m16n8k16.row.col.f32.bf16.bf16.f32 "
        "{%0,%1,%2,%3}, {%4,%5,%6,%7}, {%8,%9}, {%0,%1,%2,%3};"
        : "+f"(d[0]), "+f"(d[1]), "+f"(d[2]), "+f"(d[3])
        : "r"(a[0]), "r"(a[1]), "r"(a[2]), "r"(a[3]), "r"(b[0]), "r"(b[1]));
}

// split two floats into packed bf16x2 hi + lo(residual)
__device__ __forceinline__ void split2(float a, float b, uint32_t& hi, uint32_t& lo) {
    __nv_bfloat162 h = __floats2bfloat162_rn(a, b);
    hi = *(uint32_t*)&h;
    float ra = a - __bfloat162float(h.x);
    float rb = b - __bfloat162float(h.y);
    __nv_bfloat162 l2 = __floats2bfloat162_rn(ra, rb);
    lo = *(uint32_t*)&l2;
}

// transpose + split: W [K,N] fp32 -> hi/lo [N,K] bf16
__global__ void tsplit_kernel(const float* __restrict__ W,
                              __nv_bfloat16* __restrict__ hi,
                              __nv_bfloat16* __restrict__ lo, int K, int N)
{
    __shared__ float t[32][33];
    int k0 = blockIdx.y * 32, n0 = blockIdx.x * 32;
    int tx = threadIdx.x, ty = threadIdx.y;   // block (32,8)
#pragma unroll
    for (int i = 0; i < 32; i += 8)
        t[ty + i][tx] = W[(size_t)(k0 + ty + i) * N + n0 + tx];
    __syncthreads();
#pragma unroll
    for (int i = 0; i < 32; i += 8) {
        float v = t[tx][ty + i];
        size_t o = (size_t)(n0 + ty + i) * K + k0 + tx;
        __nv_bfloat16 h = __float2bfloat16(v);
        hi[o] = h;
        lo[o] = __float2bfloat16(v - __bfloat162float(h));
    }
}

// ---------------- mma.sync bf16 split GEMM ------------------------------------
// C[M,N] = A[M,K] @ Bt[N,K]^T + bias, fp32 accum.
// CTA tile 128x64, BK=64, 8 warps (4m x 2n), warp tile 32x32.
// AF32:  A is fp32, converted to hi/lo during the smem load phase.
// EPIROPE: epilogue applies RoPE + hi/lo split, scattering to g_qh..g_vl.
#define GBM 128
#define GBN 64
#define GBK 64
#define KPAD 72
#define OFF_AH 0
#define OFF_AL (128 * KPAD * 2)
#define OFF_BH (2 * 128 * KPAD * 2)
#define OFF_BL (2 * 128 * KPAD * 2 + 64 * KPAD * 2)
#define GSMEM  (2 * 128 * KPAD * 2 + 2 * 64 * KPAD * 2)   // 55296 B

template <int AF32, int EPIROPE>
__global__ void __launch_bounds__(256)
gemm_mma_kernel(const float* __restrict__ Af,
                const __nv_bfloat16* __restrict__ Ahi,
                const __nv_bfloat16* __restrict__ Alo,
                const __nv_bfloat16* __restrict__ Bhi,
                const __nv_bfloat16* __restrict__ Blo,
                const float* __restrict__ bias,
                const float* __restrict__ cosT,
                const float* __restrict__ sinT,
                float* __restrict__ Cm,
                int N, int K)
{
    extern __shared__ __align__(16) unsigned char smem[];
    __nv_bfloat16* sAh = (__nv_bfloat16*)(smem + OFF_AH);
    __nv_bfloat16* sAl = (__nv_bfloat16*)(smem + OFF_AL);
    __nv_bfloat16* sBh = (__nv_bfloat16*)(smem + OFF_BH);
    __nv_bfloat16* sBl = (__nv_bfloat16*)(smem + OFF_BL);
    const uint32_t sb = smem_u32(smem);

    const int tid  = threadIdx.x;
    const int lane = tid & 31;
    const int w    = tid >> 5;
    const int m_base = (w & 3) * 32;
    const int n_base = (w >> 2) * 32;

    const int m0 = blockIdx.y * GBM;
    const int n0 = blockIdx.x * GBN;

    float d[2][4][4];
#pragma unroll
    for (int i = 0; i < 2; i++)
#pragma unroll
        for (int j = 0; j < 4; j++)
#pragma unroll
            for (int r = 0; r < 4; r++) d[i][j][r] = 0.f;

    const int a_m   = m_base + (lane & 7) + ((lane >> 3) & 1) * 8;
    const int a_khi = (lane >> 4) * 8;
    const int b_g   = lane >> 3;
    const int b_n8  = (b_g >> 1) * 8 + (lane & 7);
    const int b_k8  = (b_g & 1) * 8;

    for (int k0 = 0; k0 < K; k0 += GBK) {
#pragma unroll
        for (int it = 0; it < 4; it++) {
            int u = tid + it * 256;
            int row = u >> 3, c8 = (u & 7) * 8;
            int s = row * KPAD + c8;
            if (AF32) {
                const float* gp = Af + (size_t)(m0 + row) * K + k0 + c8;
                float4 f0 = *(const float4*)gp;
                float4 f1 = *(const float4*)(gp + 4);
                uint4 vh, vl;
                split2(f0.x, f0.y, vh.x, vl.x);
                split2(f0.z, f0.w, vh.y, vl.y);
                split2(f1.x, f1.y, vh.z, vl.z);
                split2(f1.z, f1.w, vh.w, vl.w);
                *(uint4*)(sAh + s) = vh;
                *(uint4*)(sAl + s) = vl;
            } else {
                size_t g = (size_t)(m0 + row) * K + k0 + c8;
                *(uint4*)(sAh + s) = *(const uint4*)(Ahi + g);
                *(uint4*)(sAl + s) = *(const uint4*)(Alo + g);
            }
        }
#pragma unroll
        for (int it = 0; it < 2; it++) {
            int u = tid + it * 256;
            int row = u >> 3, c8 = (u & 7) * 8;
            size_t g = (size_t)(n0 + row) * K + k0 + c8;
            int s = row * KPAD + c8;
            *(uint4*)(sBh + s) = *(const uint4*)(Bhi + g);
            *(uint4*)(sBl + s) = *(const uint4*)(Blo + g);
        }
        __syncthreads();

#pragma unroll
        for (int ks = 0; ks < 4; ks++) {
            const int koff = ks * 16;
            uint32_t ah[2][4], al[2][4], bh[4][2], bl[4][2];
#pragma unroll
            for (int mf = 0; mf < 2; mf++) {
                uint32_t off = (uint32_t)((a_m + mf * 16) * KPAD + koff + a_khi) * 2;
                ldsm_x4(ah[mf], sb + OFF_AH + off);
                ldsm_x4(al[mf], sb + OFF_AL + off);
            }
#pragma unroll
            for (int pr = 0; pr < 2; pr++) {
                uint32_t off = (uint32_t)((n_base + pr * 16 + b_n8) * KPAD + koff + b_k8) * 2;
                uint32_t rh[4], rl[4];
                ldsm_x4(rh, sb + OFF_BH + off);
                ldsm_x4(rl, sb + OFF_BL + off);
                bh[pr * 2 + 0][0] = rh[0]; bh[pr * 2 + 0][1] = rh[1];
                bh[pr * 2 + 1][0] = rh[2]; bh[pr * 2 + 1][1] = rh[3];
                bl[pr * 2 + 0][0] = rl[0]; bl[pr * 2 + 0][1] = rl[1];
                bl[pr * 2 + 1][0] = rl[2]; bl[pr * 2 + 1][1] = rl[3];
            }
#pragma unroll
            for (int mf = 0; mf < 2; mf++)
#pragma unroll
                for (int nf = 0; nf < 4; nf++) {
                    mma_bf16(d[mf][nf], ah[mf], bh[nf]);
                    mma_bf16(d[mf][nf], ah[mf], bl[nf]);
                    mma_bf16(d[mf][nf], al[mf], bh[nf]);
                }
        }
        __syncthreads();
    }

    if (EPIROPE) {
        // sec/head uniform per CTA (64-col tiles never straddle 1024 boundary)
        const int sec = n0 >> 10;            // 0=q 1=k 2=v
        const int h   = (n0 & 1023) >> 6;    // head
#pragma unroll
        for (int mf = 0; mf < 2; mf++) {
            int row = m0 + m_base + mf * 16 + (lane >> 2);
#pragma unroll
            for (int rr = 0; rr < 2; rr++) {
                int r = row + rr * 8;
                int t = r & (TT - 1), b = r >> 11;
                size_t obase = ((size_t)(b * HH + h) * TT + t) * DD;
#pragma unroll
                for (int nf = 0; nf < 4; nf++) {
                    int dcol = n_base + nf * 8 + 2 * (lane & 3);   // even, 0..62
                    int col  = n0 + dcol;
                    float v0 = d[mf][nf][rr * 2 + 0] + bias[col];
                    float v1 = d[mf][nf][rr * 2 + 1] + bias[col + 1];
                    uint32_t hi, lo;
                    if (sec == 2) {
                        split2(v0, v1, hi, lo);
                        *(uint32_t*)&g_vh[obase + dcol] = hi;
                        *(uint32_t*)&g_vl[obase + dcol] = lo;
                    } else {
                        int i = dcol >> 1;
                        float c = cosT[t * 32 + i], s = sinT[t * 32 + i];
                        float r0 = v0 * c - v1 * s;
                        float r1 = v0 * s + v1 * c;
                        if (sec == 0) {
                            split2(r0 * 0.125f, r1 * 0.125f, hi, lo);
                            *(uint32_t*)&g_qh[obase + dcol] = hi;
                            *(uint32_t*)&g_ql[obase + dcol] = lo;
                        } else {
                            split2(r0, r1, hi, lo);
                            *(uint32_t*)&g_kh[obase + dcol] = hi;
                            *(uint32_t*)&g_kl[obase + dcol] = lo;
                        }
                    }
                }
            }
        }
    } else {
#pragma unroll
        for (int mf = 0; mf < 2; mf++) {
#pragma unroll
            for (int nf = 0; nf < 4; nf++) {
                int row = m0 + m_base + mf * 16 + (lane >> 2);
                int col = n0 + n_base + nf * 8 + 2 * (lane & 3);
                float bx = bias[col], by = bias[col + 1];
                float2 v0 = {d[mf][nf][0] + bx, d[mf][nf][1] + by};
                float2 v1 = {d[mf][nf][2] + bx, d[mf][nf][3] + by};
                *(float2*)&Cm[(size_t)row * N + col]       = v0;
                *(float2*)&Cm[(size_t)(row + 8) * N + col] = v1;
            }
        }
    }
}

// ---------------- tensor-core causal flash attention --------------------------
// BQ=128, BKV=64, 8 warps x 16 q-rows. Q frags register-resident; K/V per chunk.
#define FKP 72
#define F_QH 0
#define F_QL 18432
#define F_KH 0
#define F_KL 9216
#define F_VH 18432
#define F_VL 27648
#define FLASH_SMEM 36864

__global__ void __launch_bounds__(256)
flash_mma_kernel(const __nv_bfloat16* __restrict__ Qh,
                 const __nv_bfloat16* __restrict__ Ql,
                 const __nv_bfloat16* __restrict__ Kh,
                 const __nv_bfloat16* __restrict__ Kl,
                 const __nv_bfloat16* __restrict__ Vh,
                 const __nv_bfloat16* __restrict__ Vl)
{
    extern __shared__ __align__(16) unsigned char smem[];
    const uint32_t sb = smem_u32(smem);
    const int tid  = threadIdx.x;
    const int lane = tid & 31;
    const int w    = tid >> 5;

    const int qt = gridDim.x - 1 - blockIdx.x;   // heavy tiles first
    const int q0 = qt * 128;
    const int bh = blockIdx.y;
    const size_t gbase = (size_t)bh * TT * DD;

    // ---- load Q tile (hi/lo) into smem ----
#pragma unroll
    for (int it = 0; it < 4; it++) {
        int u = tid + it * 256;                  // 0..1023
        int row = u >> 3, c8 = (u & 7) * 8;
        size_t g = gbase + (size_t)(q0 + row) * DD + c8;
        int s = row * FKP + c8;
        *(uint4*)(smem + F_QH + s * 2) = *(const uint4*)(Qh + g);
        *(uint4*)(smem + F_QL + s * 2) = *(const uint4*)(Ql + g);
    }
    __syncthreads();

    // ---- Q fragments into registers ----
    const int a_m   = w * 16 + (lane & 7) + ((lane >> 3) & 1) * 8;
    const int a_khi = (lane >> 4) * 8;
    uint32_t qh[4][4], ql[4][4];
#pragma unroll
    for (int ks = 0; ks < 4; ks++) {
        uint32_t off = (uint32_t)(a_m * FKP + ks * 16 + a_khi) * 2;
        ldsm_x4(qh[ks], sb + F_QH + off);
        ldsm_x4(ql[ks], sb + F_QL + off);
    }
    __syncthreads();   // done with Q smem; reuse for K/V

    const int b_g   = lane >> 3;
    const int b_n8  = (b_g >> 1) * 8 + (lane & 7);
    const int b_k8  = (b_g & 1) * 8;
    const int v_r8  = (b_g & 1) * 8 + (lane & 7);
    const int v_c8  = (b_g >> 1) * 8;

    float o[8][4];
#pragma unroll
    for (int nf = 0; nf < 8; nf++)
#pragma unroll
        for (int j = 0; j < 4; j++) o[nf][j] = 0.f;
    float m0 = -1e30f, m1 = -1e30f, l0 = 0.f, l1 = 0.f;

    const int r0g = q0 + w * 16 + (lane >> 2);
    const int nchunk = 2 * qt + 2;

    for (int ch = 0; ch < nchunk; ch++) {
        const int kv0 = ch * 64;
        __syncthreads();   // previous chunk's smem reads done
#pragma unroll
        for (int it = 0; it < 2; it++) {
            int u = tid + it * 256;              // 0..511
            int row = u >> 3, c8 = (u & 7) * 8;
            size_t g = gbase + (size_t)(kv0 + row) * DD + c8;
            int s = (row * FKP + c8) * 2;
            *(uint4*)(smem + F_KH + s) = *(const uint4*)(Kh + g);
            *(uint4*)(smem + F_KL + s) = *(const uint4*)(Kl + g);
            *(uint4*)(smem + F_VH + s) = *(const uint4*)(Vh + g);
            *(uint4*)(smem + F_VL + s) = *(const uint4*)(Vl + g);
        }
        __syncthreads();

        // ---- S = Q K^T (3-term split) ----
        float s4[8][4];
#pragma unroll
        for (int nf = 0; nf < 8; nf++)
#pragma unroll
            for (int j = 0; j < 4; j++) s4[nf][j] = 0.f;

#pragma unroll
        for (int ks = 0; ks < 4; ks++) {
#pragma unroll
            for (int pr = 0; pr < 4; pr++) {
                uint32_t off = (uint32_t)((pr * 16 + b_n8) * FKP + ks * 16 + b_k8) * 2;
                uint32_t kh4[4], kl4[4];
                ldsm_x4(kh4, sb + F_KH + off);
                ldsm_x4(kl4, sb + F_KL + off);
                uint32_t bh0[2] = {kh4[0], kh4[1]}, bh1[2] = {kh4[2], kh4[3]};
                uint32_t bl0[2] = {kl4[0], kl4[1]}, bl1[2] = {kl4[2], kl4[3]};
                mma_bf16(s4[2 * pr], qh[ks], bh0);
                mma_bf16(s4[2 * pr], qh[ks], bl0);
                mma_bf16(s4[2 * pr], ql[ks], bh0);
                mma_bf16(s4[2 * pr + 1], qh[ks], bh1);
                mma_bf16(s4[2 * pr + 1], qh[ks], bl1);
                mma_bf16(s4[2 * pr + 1], ql[ks], bh1);
            }
        }

        // ---- causal mask (only last two chunks of this tile) ----
        if (ch >= 2 * qt) {
#pragma unroll
            for (int nf = 0; nf < 8; nf++) {
                int cbase = kv0 + nf * 8 + (lane & 3) * 2;
#pragma unroll
                for (int j = 0; j < 4; j++) {
                    int col = cbase + (j & 1);
                    int row = r0g + ((j >> 1) << 3);
                    if (col > row) s4[nf][j] = -1e30f;
                }
            }
        }

        // ---- online softmax ----
        float mx0 = -1e30f, mx1 = -1e30f;
#pragma unroll
        for (int nf = 0; nf < 8; nf++) {
            mx0 = fmaxf(mx0, fmaxf(s4[nf][0], s4[nf][1]));
            mx1 = fmaxf(mx1, fmaxf(s4[nf][2], s4[nf][3]));
        }
        mx0 = fmaxf(mx0, __shfl_xor_sync(0xffffffffu, mx0, 1));
        mx0 = fmaxf(mx0, __shfl_xor_sync(0xffffffffu, mx0, 2));
        mx1 = fmaxf(mx1, __shfl_xor_sync(0xffffffffu, mx1, 1));
        mx1 = fmaxf(mx1, __shfl_xor_sync(0xffffffffu, mx1, 2));
        float mn0 = fmaxf(m0, mx0), mn1 = fmaxf(m1, mx1);
        float al0 = __expf(m0 - mn0), al1 = __expf(m1 - mn1);
        float sum0 = 0.f, sum1 = 0.f;
#pragma unroll
        for (int nf = 0; nf < 8; nf++) {
            s4[nf][0] = __expf(s4[nf][0] - mn0);
            s4[nf][1] = __expf(s4[nf][1] - mn0);
            s4[nf][2] = __expf(s4[nf][2] - mn1);
            s4[nf][3] = __expf(s4[nf][3] - mn1);
            sum0 += s4[nf][0] + s4[nf][1];
            sum1 += s4[nf][2] + s4[nf][3];
        }
        sum0 += __shfl_xor_sync(0xffffffffu, sum0, 1);
        sum0 += __shfl_xor_sync(0xffffffffu, sum0, 2);
        sum1 += __shfl_xor_sync(0xffffffffu, sum1, 1);
        sum1 += __shfl_xor_sync(0xffffffffu, sum1, 2);
        l0 = l0 * al0 + sum0;  m0 = mn0;
        l1 = l1 * al1 + sum1;  m1 = mn1;
#pragma unroll
        for (int nf = 0; nf < 8; nf++) {
            o[nf][0] *= al0; o[nf][1] *= al0;
            o[nf][2] *= al1; o[nf][3] *= al1;
        }

        // ---- O += P V (3-term split, P from registers) ----
#pragma unroll
        for (int ks = 0; ks < 4; ks++) {
            uint32_t pa_h[4], pa_l[4];
            split2(s4[2 * ks][0],     s4[2 * ks][1],     pa_h[0], pa_l[0]);
            split2(s4[2 * ks][2],     s4[2 * ks][3],     pa_h[1], pa_l[1]);
            split2(s4[2 * ks + 1][0], s4[2 * ks + 1][1], pa_h[2], pa_l[2]);
            split2(s4[2 * ks + 1][2], s4[2 * ks + 1][3], pa_h[3], pa_l[3]);
#pragma unroll
            for (int pr = 0; pr < 4; pr++) {
                uint32_t off = (uint32_t)((ks * 16 + v_r8) * FKP + pr * 16 + v_c8) * 2;
                uint32_t vh4[4], vl4[4];
                ldsm_x4_t(vh4, sb + F_VH + off);
                ldsm_x4_t(vl4, sb + F_VL + off);
                uint32_t bh0[2] = {vh4[0], vh4[1]}, bh1[2] = {vh4[2], vh4[3]};
                uint32_t bl0[2] = {vl4[0], vl4[1]}, bl1[2] = {vl4[2], vl4[3]};
                mma_bf16(o[2 * pr], pa_h, bh0);
                mma_bf16(o[2 * pr], pa_h, bl0);
                mma_bf16(o[2 * pr], pa_l, bh0);
                mma_bf16(o[2 * pr + 1], pa_h, bh1);
                mma_bf16(o[2 * pr + 1], pa_h, bl1);
                mma_bf16(o[2 * pr + 1], pa_l, bh1);
            }
        }
    }

    // ---- epilogue: O /= l, write bf16 hi/lo to [B,T,C] ----
    float inv0 = 1.f / l0, inv1 = 1.f / l1;
    int b = bh >> 4, h = bh & 15;
    size_t base0 = ((size_t)(b * TT + r0g)) * CC + h * DD;
    size_t base1 = ((size_t)(b * TT + r0g + 8)) * CC + h * DD;
#pragma unroll
    for (int nf = 0; nf < 8; nf++) {
        int c = nf * 8 + (lane & 3) * 2;
        uint32_t hi, lo;
        split2(o[nf][0] * inv0, o[nf][1] * inv0, hi, lo);
        *(uint32_t*)&g_yhi[base0 + c] = hi;
        *(uint32_t*)&g_ylo[base0 + c] = lo;
        split2(o[nf][2] * inv1, o[nf][3] * inv1, hi, lo);
        *(uint32_t*)&g_yhi[base1 + c] = hi;
        *(uint32_t*)&g_ylo[base1 + c] = lo;
    }
}

// ---------------- launcher ----------------------------------------------------
extern "C" void kernel_launch(void* const* d_in, const int* in_sizes, int n_in,
                              void* d_out, int out_size)
{
    const float* x     = (const float*)d_in[0];
    const float* Wqkv  = (const float*)d_in[1];
    const float* bqkv  = (const float*)d_in[2];
    const float* Wproj = (const float*)d_in[3];
    const float* bproj = (const float*)d_in[4];
    const float* cosT  = (const float*)d_in[5];
    const float* sinT  = (const float*)d_in[6];
    float* out = (float*)d_out;

    __nv_bfloat16 *wqhi, *wqlo, *wphi, *wplo, *yhi, *ylo;
    __nv_bfloat16 *qh, *ql, *kh, *kl, *vh, *vl;
    cudaGetSymbolAddress((void**)&wqhi, g_wqhi);
    cudaGetSymbolAddress((void**)&wqlo, g_wqlo);
    cudaGetSymbolAddress((void**)&wphi, g_wphi);
    cudaGetSymbolAddress((void**)&wplo, g_wplo);
    cudaGetSymbolAddress((void**)&yhi,  g_yhi);
    cudaGetSymbolAddress((void**)&ylo,  g_ylo);
    cudaGetSymbolAddress((void**)&qh,   g_qh);
    cudaGetSymbolAddress((void**)&ql,   g_ql);
    cudaGetSymbolAddress((void**)&kh,   g_kh);
    cudaGetSymbolAddress((void**)&kl,   g_kl);
    cudaGetSymbolAddress((void**)&vh,   g_vh);
    cudaGetSymbolAddress((void**)&vl,   g_vl);

    static bool attr_set = false;
    if (!attr_set) {
        cudaFuncSetAttribute(gemm_mma_kernel<1, 1>,
                             cudaFuncAttributeMaxDynamicSharedMemorySize, GSMEM);
        cudaFuncSetAttribute(gemm_mma_kernel<0, 0>,
                             cudaFuncAttributeMaxDynamicSharedMemorySize, GSMEM);
        cudaFuncSetAttribute(flash_mma_kernel,
                             cudaFuncAttributeMaxDynamicSharedMemorySize, FLASH_SMEM);
        attr_set = true;
    }

    // pre-pass: transpose+split weights
    tsplit_kernel<<<dim3(C3 / 32, CC / 32), dim3(32, 8)>>>(Wqkv, wqhi, wqlo, CC, C3);
    tsplit_kernel<<<dim3(CC / 32, CC / 32), dim3(32, 8)>>>(Wproj, wphi, wplo, CC, CC);

    // 1) QKV projection, fused bias+RoPE+split epilogue -> g_qh..g_vl
    gemm_mma_kernel<1, 1><<<dim3(C3 / GBN, MM / GBM), 256, GSMEM>>>(
        x, nullptr, nullptr, wqhi, wqlo, bqkv, cosT, sinT, nullptr, C3, CC);

    // 2) tensor-core causal flash attention (writes yhi/ylo in [B,T,C])
    flash_mma_kernel<<<dim3(TT / 128, BB * HH), 256, FLASH_SMEM>>>(
        qh, ql, kh, kl, vh, vl);

    // 3) output projection
    gemm_mma_kernel<0, 0><<<dim3(CC / GBN, MM / GBM), 256, GSMEM>>>(
        nullptr, yhi, ylo, wphi, wplo, bproj, nullptr, nullptr, out, CC, CC);
}

// round 10
// speedup vs baseline: 1.4520x; 1.0149x over previous
#include <cuda_runtime.h>
#include <cuda_bf16.h>
#include <cstdint>

#define BB   2
#define TT   2048
#define CC   1024
#define HH   16
#define DD   64
#define C3   3072
#define MM   (BB * TT)        // 4096

// ---------------- scratch (static device globals; no allocations) -------------
__device__ __nv_bfloat16 g_wqhi[C3 * CC];          // Wqkv^T split [N,K]
__device__ __nv_bfloat16 g_wqlo[C3 * CC];
__device__ __nv_bfloat16 g_wphi[CC * CC];          // Wproj^T split [N,K]
__device__ __nv_bfloat16 g_wplo[CC * CC];
__device__ __nv_bfloat16 g_yhi[MM * CC];           // attention out split [B,T,C]
__device__ __nv_bfloat16 g_ylo[MM * CC];

// Q/K/V bf16 hi/lo in [B,H,T,D] (Q pre-scaled by 1/8)
__device__ __nv_bfloat16 g_qh[MM * CC];
__device__ __nv_bfloat16 g_ql[MM * CC];
__device__ __nv_bfloat16 g_kh[MM * CC];
__device__ __nv_bfloat16 g_kl[MM * CC];
__device__ __nv_bfloat16 g_vh[MM * CC];
__device__ __nv_bfloat16 g_vl[MM * CC];

// ---------------- helpers ------------------------------------------------------
__device__ __forceinline__ uint32_t smem_u32(const void* p) {
    uint32_t a;
    asm("{ .reg .u64 t; cvta.to.shared.u64 t, %1; cvt.u32.u64 %0, t; }"
        : "=r"(a) : "l"(p));
    return a;
}

__device__ __forceinline__ void ldsm_x4(uint32_t r[4], uint32_t addr) {
    asm volatile("ldmatrix.sync.aligned.m8n8.x4.shared.b16 {%0,%1,%2,%3}, [%4];"
                 : "=r"(r[0]), "=r"(r[1]), "=r"(r[2]), "=r"(r[3]) : "r"(addr));
}

__device__ __forceinline__ void ldsm_x4_t(uint32_t r[4], uint32_t addr) {
    asm volatile("ldmatrix.sync.aligned.m8n8.x4.trans.shared.b16 {%0,%1,%2,%3}, [%4];"
                 : "=r"(r[0]), "=r"(r[1]), "=r"(r[2]), "=r"(r[3]) : "r"(addr));
}

__device__ __forceinline__ void mma_bf16(float d[4], const uint32_t a[4],
                                         const uint32_t b[2]) {
    asm volatile(
        "mma.sync.aligned.m16n8k16.row.col.f32.bf16.bf16.f32 "
        "{%0,%1,%2,%3}, {%4,%5,%6,%7}, {%8,%9}, {%0,%1,%2,%3};"
        : "+f"(d[0]), "+f"(d[1]), "+f"(d[2]), "+f"(d[3])
        : "r"(a[0]), "r"(a[1]), "r"(a[2]), "r"(a[3]), "r"(b[0]), "r"(b[1]));
}

// split two floats into packed bf16x2 hi + lo(residual)
__device__ __forceinline__ void split2(float a, float b, uint32_t& hi, uint32_t& lo) {
    __nv_bfloat162 h = __floats2bfloat162_rn(a, b);
    hi = *(uint32_t*)&h;
    float ra = a - __bfloat162float(h.x);
    float rb = b - __bfloat162float(h.y);
    __nv_bfloat162 l2 = __floats2bfloat162_rn(ra, rb);
    lo = *(uint32_t*)&l2;
}

// transpose + split: W [K,N] fp32 -> hi/lo [N,K] bf16
__global__ void tsplit_kernel(const float* __restrict__ W,
                              __nv_bfloat16* __restrict__ hi,
                              __nv_bfloat16* __restrict__ lo, int K, int N)
{
    __shared__ float t[32][33];
    int k0 = blockIdx.y * 32, n0 = blockIdx.x * 32;
    int tx = threadIdx.x, ty = threadIdx.y;   // block (32,8)
#pragma unroll
    for (int i = 0; i < 32; i += 8)
        t[ty + i][tx] = W[(size_t)(k0 + ty + i) * N + n0 + tx];
    __syncthreads();
#pragma unroll
    for (int i = 0; i < 32; i += 8) {
        float v = t[tx][ty + i];
        size_t o = (size_t)(n0 + ty + i) * K + k0 + tx;
        __nv_bfloat16 h = __float2bfloat16(v);
        hi[o] = h;
        lo[o] = __float2bfloat16(v - __bfloat162float(h));
    }
}

// ---------------- mma.sync bf16 split GEMM ------------------------------------
// C[M,N] = A[M,K] @ Bt[N,K]^T + bias, fp32 accum.
// CTA tile 128x64, BK=64, 8 warps (4m x 2n), warp tile 32x32.
// AF32:  A is fp32, converted to hi/lo during the smem load phase.
// EPIROPE: epilogue applies RoPE + hi/lo split, scattering to g_qh..g_vl.
#define GBM 128
#define GBN 64
#define GBK 64
#define KPAD 72
#define OFF_AH 0
#define OFF_AL (128 * KPAD * 2)
#define OFF_BH (2 * 128 * KPAD * 2)
#define OFF_BL (2 * 128 * KPAD * 2 + 64 * KPAD * 2)
#define GSMEM  (2 * 128 * KPAD * 2 + 2 * 64 * KPAD * 2)   // 55296 B

template <int AF32, int EPIROPE>
__global__ void __launch_bounds__(256)
gemm_mma_kernel(const float* __restrict__ Af,
                const __nv_bfloat16* __restrict__ Ahi,
                const __nv_bfloat16* __restrict__ Alo,
                const __nv_bfloat16* __restrict__ Bhi,
                const __nv_bfloat16* __restrict__ Blo,
                const float* __restrict__ bias,
                const float* __restrict__ cosT,
                const float* __restrict__ sinT,
                float* __restrict__ Cm,
                int N, int K)
{
    extern __shared__ __align__(16) unsigned char smem[];
    __nv_bfloat16* sAh = (__nv_bfloat16*)(smem + OFF_AH);
    __nv_bfloat16* sAl = (__nv_bfloat16*)(smem + OFF_AL);
    __nv_bfloat16* sBh = (__nv_bfloat16*)(smem + OFF_BH);
    __nv_bfloat16* sBl = (__nv_bfloat16*)(smem + OFF_BL);
    const uint32_t sb = smem_u32(smem);

    const int tid  = threadIdx.x;
    const int lane = tid & 31;
    const int w    = tid >> 5;
    const int m_base = (w & 3) * 32;
    const int n_base = (w >> 2) * 32;

    const int m0 = blockIdx.y * GBM;
    const int n0 = blockIdx.x * GBN;

    float d[2][4][4];
#pragma unroll
    for (int i = 0; i < 2; i++)
#pragma unroll
        for (int j = 0; j < 4; j++)
#pragma unroll
            for (int r = 0; r < 4; r++) d[i][j][r] = 0.f;

    const int a_m   = m_base + (lane & 7) + ((lane >> 3) & 1) * 8;
    const int a_khi = (lane >> 4) * 8;
    const int b_g   = lane >> 3;
    const int b_n8  = (b_g >> 1) * 8 + (lane & 7);
    const int b_k8  = (b_g & 1) * 8;

    for (int k0 = 0; k0 < K; k0 += GBK) {
#pragma unroll
        for (int it = 0; it < 4; it++) {
            int u = tid + it * 256;
            int row = u >> 3, c8 = (u & 7) * 8;
            int s = row * KPAD + c8;
            if (AF32) {
                const float* gp = Af + (size_t)(m0 + row) * K + k0 + c8;
                float4 f0 = *(const float4*)gp;
                float4 f1 = *(const float4*)(gp + 4);
                uint4 vh, vl;
                split2(f0.x, f0.y, vh.x, vl.x);
                split2(f0.z, f0.w, vh.y, vl.y);
                split2(f1.x, f1.y, vh.z, vl.z);
                split2(f1.z, f1.w, vh.w, vl.w);
                *(uint4*)(sAh + s) = vh;
                *(uint4*)(sAl + s) = vl;
            } else {
                size_t g = (size_t)(m0 + row) * K + k0 + c8;
                *(uint4*)(sAh + s) = *(const uint4*)(Ahi + g);
                *(uint4*)(sAl + s) = *(const uint4*)(Alo + g);
            }
        }
#pragma unroll
        for (int it = 0; it < 2; it++) {
            int u = tid + it * 256;
            int row = u >> 3, c8 = (u & 7) * 8;
            size_t g = (size_t)(n0 + row) * K + k0 + c8;
            int s = row * KPAD + c8;
            *(uint4*)(sBh + s) = *(const uint4*)(Bhi + g);
            *(uint4*)(sBl + s) = *(const uint4*)(Blo + g);
        }
        __syncthreads();

#pragma unroll
        for (int ks = 0; ks < 4; ks++) {
            const int koff = ks * 16;
            uint32_t ah[2][4], al[2][4], bh[4][2], bl[4][2];
#pragma unroll
            for (int mf = 0; mf < 2; mf++) {
                uint32_t off = (uint32_t)((a_m + mf * 16) * KPAD + koff + a_khi) * 2;
                ldsm_x4(ah[mf], sb + OFF_AH + off);
                ldsm_x4(al[mf], sb + OFF_AL + off);
            }
#pragma unroll
            for (int pr = 0; pr < 2; pr++) {
                uint32_t off = (uint32_t)((n_base + pr * 16 + b_n8) * KPAD + koff + b_k8) * 2;
                uint32_t rh[4], rl[4];
                ldsm_x4(rh, sb + OFF_BH + off);
                ldsm_x4(rl, sb + OFF_BL + off);
                bh[pr * 2 + 0][0] = rh[0]; bh[pr * 2 + 0][1] = rh[1];
                bh[pr * 2 + 1][0] = rh[2]; bh[pr * 2 + 1][1] = rh[3];
                bl[pr * 2 + 0][0] = rl[0]; bl[pr * 2 + 0][1] = rl[1];
                bl[pr * 2 + 1][0] = rl[2]; bl[pr * 2 + 1][1] = rl[3];
            }
#pragma unroll
            for (int mf = 0; mf < 2; mf++)
#pragma unroll
                for (int nf = 0; nf < 4; nf++) {
                    mma_bf16(d[mf][nf], ah[mf], bh[nf]);
                    mma_bf16(d[mf][nf], ah[mf], bl[nf]);
                    mma_bf16(d[mf][nf], al[mf], bh[nf]);
                }
        }
        __syncthreads();
    }

    if (EPIROPE) {
        // sec/head uniform per CTA (64-col tiles never straddle 1024 boundary)
        const int sec = n0 >> 10;            // 0=q 1=k 2=v
        const int h   = (n0 & 1023) >> 6;    // head
#pragma unroll
        for (int mf = 0; mf < 2; mf++) {
            int row = m0 + m_base + mf * 16 + (lane >> 2);
#pragma unroll
            for (int rr = 0; rr < 2; rr++) {
                int r = row + rr * 8;
                int t = r & (TT - 1), b = r >> 11;
                size_t obase = ((size_t)(b * HH + h) * TT + t) * DD;
#pragma unroll
                for (int nf = 0; nf < 4; nf++) {
                    int dcol = n_base + nf * 8 + 2 * (lane & 3);   // even, 0..62
                    int col  = n0 + dcol;
                    float v0 = d[mf][nf][rr * 2 + 0] + bias[col];
                    float v1 = d[mf][nf][rr * 2 + 1] + bias[col + 1];
                    uint32_t hi, lo;
                    if (sec == 2) {
                        split2(v0, v1, hi, lo);
                        *(uint32_t*)&g_vh[obase + dcol] = hi;
                        *(uint32_t*)&g_vl[obase + dcol] = lo;
                    } else {
                        int i = dcol >> 1;
                        float c = cosT[t * 32 + i], s = sinT[t * 32 + i];
                        float r0 = v0 * c - v1 * s;
                        float r1 = v0 * s + v1 * c;
                        if (sec == 0) {
                            split2(r0 * 0.125f, r1 * 0.125f, hi, lo);
                            *(uint32_t*)&g_qh[obase + dcol] = hi;
                            *(uint32_t*)&g_ql[obase + dcol] = lo;
                        } else {
                            split2(r0, r1, hi, lo);
                            *(uint32_t*)&g_kh[obase + dcol] = hi;
                            *(uint32_t*)&g_kl[obase + dcol] = lo;
                        }
                    }
                }
            }
        }
    } else {
#pragma unroll
        for (int mf = 0; mf < 2; mf++) {
#pragma unroll
            for (int nf = 0; nf < 4; nf++) {
                int row = m0 + m_base + mf * 16 + (lane >> 2);
                int col = n0 + n_base + nf * 8 + 2 * (lane & 3);
                float bx = bias[col], by = bias[col + 1];
                float2 v0 = {d[mf][nf][0] + bx, d[mf][nf][1] + by};
                float2 v1 = {d[mf][nf][2] + bx, d[mf][nf][3] + by};
                *(float2*)&Cm[(size_t)row * N + col]       = v0;
                *(float2*)&Cm[(size_t)(row + 8) * N + col] = v1;
            }
        }
    }
}

// ---------------- tensor-core causal flash attention --------------------------
// BQ=128, BKV=64, 8 warps x 16 q-rows. Q frags register-resident; K/V per chunk.
// __launch_bounds__(256, 2): cap regs at 128 so 2 CTAs co-reside per SM and
// one CTA's softmax overlaps the other's MMAs.
#define FKP 72
#define F_QH 0
#define F_QL 18432
#define F_KH 0
#define F_KL 9216
#define F_VH 18432
#define F_VL 27648
#define FLASH_SMEM 36864

__global__ void __launch_bounds__(256, 2)
flash_mma_kernel(const __nv_bfloat16* __restrict__ Qh,
                 const __nv_bfloat16* __restrict__ Ql,
                 const __nv_bfloat16* __restrict__ Kh,
                 const __nv_bfloat16* __restrict__ Kl,
                 const __nv_bfloat16* __restrict__ Vh,
                 const __nv_bfloat16* __restrict__ Vl)
{
    extern __shared__ __align__(16) unsigned char smem[];
    const uint32_t sb = smem_u32(smem);
    const int tid  = threadIdx.x;
    const int lane = tid & 31;
    const int w    = tid >> 5;

    const int qt = gridDim.x - 1 - blockIdx.x;   // heavy tiles first
    const int q0 = qt * 128;
    const int bh = blockIdx.y;
    const size_t gbase = (size_t)bh * TT * DD;

    // ---- load Q tile (hi/lo) into smem ----
#pragma unroll
    for (int it = 0; it < 4; it++) {
        int u = tid + it * 256;                  // 0..1023
        int row = u >> 3, c8 = (u & 7) * 8;
        size_t g = gbase + (size_t)(q0 + row) * DD + c8;
        int s = row * FKP + c8;
        *(uint4*)(smem + F_QH + s * 2) = *(const uint4*)(Qh + g);
        *(uint4*)(smem + F_QL + s * 2) = *(const uint4*)(Ql + g);
    }
    __syncthreads();

    // ---- Q fragments into registers ----
    const int a_m   = w * 16 + (lane & 7) + ((lane >> 3) & 1) * 8;
    const int a_khi = (lane >> 4) * 8;
    uint32_t qh[4][4], ql[4][4];
#pragma unroll
    for (int ks = 0; ks < 4; ks++) {
        uint32_t off = (uint32_t)(a_m * FKP + ks * 16 + a_khi) * 2;
        ldsm_x4(qh[ks], sb + F_QH + off);
        ldsm_x4(ql[ks], sb + F_QL + off);
    }
    __syncthreads();   // done with Q smem; reuse for K/V

    const int b_g   = lane >> 3;
    const int b_n8  = (b_g >> 1) * 8 + (lane & 7);
    const int b_k8  = (b_g & 1) * 8;
    const int v_r8  = (b_g & 1) * 8 + (lane & 7);
    const int v_c8  = (b_g >> 1) * 8;

    float o[8][4];
#pragma unroll
    for (int nf = 0; nf < 8; nf++)
#pragma unroll
        for (int j = 0; j < 4; j++) o[nf][j] = 0.f;
    float m0 = -1e30f, m1 = -1e30f, l0 = 0.f, l1 = 0.f;

    const int r0g = q0 + w * 16 + (lane >> 2);
    const int nchunk = 2 * qt + 2;

    for (int ch = 0; ch < nchunk; ch++) {
        const int kv0 = ch * 64;
        __syncthreads();   // previous chunk's smem reads done
#pragma unroll
        for (int it = 0; it < 2; it++) {
            int u = tid + it * 256;              // 0..511
            int row = u >> 3, c8 = (u & 7) * 8;
            size_t g = gbase + (size_t)(kv0 + row) * DD + c8;
            int s = (row * FKP + c8) * 2;
            *(uint4*)(smem + F_KH + s) = *(const uint4*)(Kh + g);
            *(uint4*)(smem + F_KL + s) = *(const uint4*)(Kl + g);
            *(uint4*)(smem + F_VH + s) = *(const uint4*)(Vh + g);
            *(uint4*)(smem + F_VL + s) = *(const uint4*)(Vl + g);
        }
        __syncthreads();

        // ---- S = Q K^T (3-term split) ----
        float s4[8][4];
#pragma unroll
        for (int nf = 0; nf < 8; nf++)
#pragma unroll
            for (int j = 0; j < 4; j++) s4[nf][j] = 0.f;

#pragma unroll
        for (int ks = 0; ks < 4; ks++) {
#pragma unroll
            for (int pr = 0; pr < 4; pr++) {
                uint32_t off = (uint32_t)((pr * 16 + b_n8) * FKP + ks * 16 + b_k8) * 2;
                uint32_t kh4[4], kl4[4];
                ldsm_x4(kh4, sb + F_KH + off);
                ldsm_x4(kl4, sb + F_KL + off);
                uint32_t bh0[2] = {kh4[0], kh4[1]}, bh1[2] = {kh4[2], kh4[3]};
                uint32_t bl0[2] = {kl4[0], kl4[1]}, bl1[2] = {kl4[2], kl4[3]};
                mma_bf16(s4[2 * pr], qh[ks], bh0);
                mma_bf16(s4[2 * pr], qh[ks], bl0);
                mma_bf16(s4[2 * pr], ql[ks], bh0);
                mma_bf16(s4[2 * pr + 1], qh[ks], bh1);
                mma_bf16(s4[2 * pr + 1], qh[ks], bl1);
                mma_bf16(s4[2 * pr + 1], ql[ks], bh1);
            }
        }

        // ---- causal mask (only last two chunks of this tile) ----
        if (ch >= 2 * qt) {
#pragma unroll
            for (int nf = 0; nf < 8; nf++) {
                int cbase = kv0 + nf * 8 + (lane & 3) * 2;
#pragma unroll
                for (int j = 0; j < 4; j++) {
                    int col = cbase + (j & 1);
                    int row = r0g + ((j >> 1) << 3);
                    if (col > row) s4[nf][j] = -1e30f;
                }
            }
        }

        // ---- online softmax ----
        float mx0 = -1e30f, mx1 = -1e30f;
#pragma unroll
        for (int nf = 0; nf < 8; nf++) {
            mx0 = fmaxf(mx0, fmaxf(s4[nf][0], s4[nf][1]));
            mx1 = fmaxf(mx1, fmaxf(s4[nf][2], s4[nf][3]));
        }
        mx0 = fmaxf(mx0, __shfl_xor_sync(0xffffffffu, mx0, 1));
        mx0 = fmaxf(mx0, __shfl_xor_sync(0xffffffffu, mx0, 2));
        mx1 = fmaxf(mx1, __shfl_xor_sync(0xffffffffu, mx1, 1));
        mx1 = fmaxf(mx1, __shfl_xor_sync(0xffffffffu, mx1, 2));
        float mn0 = fmaxf(m0, mx0), mn1 = fmaxf(m1, mx1);
        float al0 = __expf(m0 - mn0), al1 = __expf(m1 - mn1);
        float sum0 = 0.f, sum1 = 0.f;
#pragma unroll
        for (int nf = 0; nf < 8; nf++) {
            s4[nf][0] = __expf(s4[nf][0] - mn0);
            s4[nf][1] = __expf(s4[nf][1] - mn0);
            s4[nf][2] = __expf(s4[nf][2] - mn1);
            s4[nf][3] = __expf(s4[nf][3] - mn1);
            sum0 += s4[nf][0] + s4[nf][1];
            sum1 += s4[nf][2] + s4[nf][3];
        }
        sum0 += __shfl_xor_sync(0xffffffffu, sum0, 1);
        sum0 += __shfl_xor_sync(0xffffffffu, sum0, 2);
        sum1 += __shfl_xor_sync(0xffffffffu, sum1, 1);
        sum1 += __shfl_xor_sync(0xffffffffu, sum1, 2);
        l0 = l0 * al0 + sum0;  m0 = mn0;
        l1 = l1 * al1 + sum1;  m1 = mn1;
#pragma unroll
        for (int nf = 0; nf < 8; nf++) {
            o[nf][0] *= al0; o[nf][1] *= al0;
            o[nf][2] *= al1; o[nf][3] *= al1;
        }

        // ---- O += P V (3-term split, P from registers) ----
#pragma unroll
        for (int ks = 0; ks < 4; ks++) {
            uint32_t pa_h[4], pa_l[4];
            split2(s4[2 * ks][0],     s4[2 * ks][1],     pa_h[0], pa_l[0]);
            split2(s4[2 * ks][2],     s4[2 * ks][3],     pa_h[1], pa_l[1]);
            split2(s4[2 * ks + 1][0], s4[2 * ks + 1][1], pa_h[2], pa_l[2]);
            split2(s4[2 * ks + 1][2], s4[2 * ks + 1][3], pa_h[3], pa_l[3]);
#pragma unroll
            for (int pr = 0; pr < 4; pr++) {
                uint32_t off = (uint32_t)((ks * 16 + v_r8) * FKP + pr * 16 + v_c8) * 2;
                uint32_t vh4[4], vl4[4];
                ldsm_x4_t(vh4, sb + F_VH + off);
                ldsm_x4_t(vl4, sb + F_VL + off);
                uint32_t bh0[2] = {vh4[0], vh4[1]}, bh1[2] = {vh4[2], vh4[3]};
                uint32_t bl0[2] = {vl4[0], vl4[1]}, bl1[2] = {vl4[2], vl4[3]};
                mma_bf16(o[2 * pr], pa_h, bh0);
                mma_bf16(o[2 * pr], pa_h, bl0);
                mma_bf16(o[2 * pr], pa_l, bh0);
                mma_bf16(o[2 * pr + 1], pa_h, bh1);
                mma_bf16(o[2 * pr + 1], pa_h, bl1);
                mma_bf16(o[2 * pr + 1], pa_l, bh1);
            }
        }
    }

    // ---- epilogue: O /= l, write bf16 hi/lo to [B,T,C] ----
    float inv0 = 1.f / l0, inv1 = 1.f / l1;
    int b = bh >> 4, h = bh & 15;
    size_t base0 = ((size_t)(b * TT + r0g)) * CC + h * DD;
    size_t base1 = ((size_t)(b * TT + r0g + 8)) * CC + h * DD;
#pragma unroll
    for (int nf = 0; nf < 8; nf++) {
        int c = nf * 8 + (lane & 3) * 2;
        uint32_t hi, lo;
        split2(o[nf][0] * inv0, o[nf][1] * inv0, hi, lo);
        *(uint32_t*)&g_yhi[base0 + c] = hi;
        *(uint32_t*)&g_ylo[base0 + c] = lo;
        split2(o[nf][2] * inv1, o[nf][3] * inv1, hi, lo);
        *(uint32_t*)&g_yhi[base1 + c] = hi;
        *(uint32_t*)&g_ylo[base1 + c] = lo;
    }
}

// ---------------- launcher ----------------------------------------------------
extern "C" void kernel_launch(void* const* d_in, const int* in_sizes, int n_in,
                              void* d_out, int out_size)
{
    const float* x     = (const float*)d_in[0];
    const float* Wqkv  = (const float*)d_in[1];
    const float* bqkv  = (const float*)d_in[2];
    const float* Wproj = (const float*)d_in[3];
    const float* bproj = (const float*)d_in[4];
    const float* cosT  = (const float*)d_in[5];
    const float* sinT  = (const float*)d_in[6];
    float* out = (float*)d_out;

    __nv_bfloat16 *wqhi, *wqlo, *wphi, *wplo, *yhi, *ylo;
    __nv_bfloat16 *qh, *ql, *kh, *kl, *vh, *vl;
    cudaGetSymbolAddress((void**)&wqhi, g_wqhi);
    cudaGetSymbolAddress((void**)&wqlo, g_wqlo);
    cudaGetSymbolAddress((void**)&wphi, g_wphi);
    cudaGetSymbolAddress((void**)&wplo, g_wplo);
    cudaGetSymbolAddress((void**)&yhi,  g_yhi);
    cudaGetSymbolAddress((void**)&ylo,  g_ylo);
    cudaGetSymbolAddress((void**)&qh,   g_qh);
    cudaGetSymbolAddress((void**)&ql,   g_ql);
    cudaGetSymbolAddress((void**)&kh,   g_kh);
    cudaGetSymbolAddress((void**)&kl,   g_kl);
    cudaGetSymbolAddress((void**)&vh,   g_vh);
    cudaGetSymbolAddress((void**)&vl,   g_vl);

    static bool attr_set = false;
    if (!attr_set) {
        cudaFuncSetAttribute(gemm_mma_kernel<1, 1>,
                             cudaFuncAttributeMaxDynamicSharedMemorySize, GSMEM);
        cudaFuncSetAttribute(gemm_mma_kernel<0, 0>,
                             cudaFuncAttributeMaxDynamicSharedMemorySize, GSMEM);
        cudaFuncSetAttribute(flash_mma_kernel,
                             cudaFuncAttributeMaxDynamicSharedMemorySize, FLASH_SMEM);
        attr_set = true;
    }

    // pre-pass: transpose+split weights
    tsplit_kernel<<<dim3(C3 / 32, CC / 32), dim3(32, 8)>>>(Wqkv, wqhi, wqlo, CC, C3);
    tsplit_kernel<<<dim3(CC / 32, CC / 32), dim3(32, 8)>>>(Wproj, wphi, wplo, CC, CC);

    // 1) QKV projection, fused bias+RoPE+split epilogue -> g_qh..g_vl
    gemm_mma_kernel<1, 1><<<dim3(C3 / GBN, MM / GBM), 256, GSMEM>>>(
        x, nullptr, nullptr, wqhi, wqlo, bqkv, cosT, sinT, nullptr, C3, CC);

    // 2) tensor-core causal flash attention (writes yhi/ylo in [B,T,C])
    flash_mma_kernel<<<dim3(TT / 128, BB * HH), 256, FLASH_SMEM>>>(
        qh, ql, kh, kl, vh, vl);

    // 3) output projection
    gemm_mma_kernel<0, 0><<<dim3(CC / GBN, MM / GBM), 256, GSMEM>>>(
        nullptr, yhi, ylo, wphi, wplo, bproj, nullptr, nullptr, out, CC, CC);
}

// round 11
// speedup vs baseline: 1.5178x; 1.0453x over previous
#include <cuda_runtime.h>
#include <cuda_bf16.h>
#include <cstdint>

#define BB   2
#define TT   2048
#define CC   1024
#define HH   16
#define DD   64
#define C3   3072
#define MM   (BB * TT)        // 4096

// ---------------- scratch (static device globals; no allocations) -------------
__device__ __nv_bfloat16 g_xhi[MM * CC];           // x split [M,K]
__device__ __nv_bfloat16 g_xlo[MM * CC];
__device__ __nv_bfloat16 g_wqhi[C3 * CC];          // Wqkv^T split [N,K]
__device__ __nv_bfloat16 g_wqlo[C3 * CC];
__device__ __nv_bfloat16 g_wphi[CC * CC];          // Wproj^T split [N,K]
__device__ __nv_bfloat16 g_wplo[CC * CC];
__device__ __nv_bfloat16 g_yhi[MM * CC];           // attention out split [B,T,C]
__device__ __nv_bfloat16 g_ylo[MM * CC];

// Q/K/V bf16 hi/lo in [B,H,T,D] (Q pre-scaled by 1/8)
__device__ __nv_bfloat16 g_qh[MM * CC];
__device__ __nv_bfloat16 g_ql[MM * CC];
__device__ __nv_bfloat16 g_kh[MM * CC];
__device__ __nv_bfloat16 g_kl[MM * CC];
__device__ __nv_bfloat16 g_vh[MM * CC];
__device__ __nv_bfloat16 g_vl[MM * CC];

// ---------------- helpers ------------------------------------------------------
__device__ __forceinline__ uint32_t smem_u32(const void* p) {
    uint32_t a;
    asm("{ .reg .u64 t; cvta.to.shared.u64 t, %1; cvt.u32.u64 %0, t; }"
        : "=r"(a) : "l"(p));
    return a;
}

__device__ __forceinline__ void ldsm_x4(uint32_t r[4], uint32_t addr) {
    asm volatile("ldmatrix.sync.aligned.m8n8.x4.shared.b16 {%0,%1,%2,%3}, [%4];"
                 : "=r"(r[0]), "=r"(r[1]), "=r"(r[2]), "=r"(r[3]) : "r"(addr));
}

__device__ __forceinline__ void ldsm_x4_t(uint32_t r[4], uint32_t addr) {
    asm volatile("ldmatrix.sync.aligned.m8n8.x4.trans.shared.b16 {%0,%1,%2,%3}, [%4];"
                 : "=r"(r[0]), "=r"(r[1]), "=r"(r[2]), "=r"(r[3]) : "r"(addr));
}

__device__ __forceinline__ void mma_bf16(float d[4], const uint32_t a[4],
                                         const uint32_t b[2]) {
    asm volatile(
        "mma.sync.aligned.m16n8k16.row.col.f32.bf16.bf16.f32 "
        "{%0,%1,%2,%3}, {%4,%5,%6,%7}, {%8,%9}, {%0,%1,%2,%3};"
        : "+f"(d[0]), "+f"(d[1]), "+f"(d[2]), "+f"(d[3])
        : "r"(a[0]), "r"(a[1]), "r"(a[2]), "r"(a[3]), "r"(b[0]), "r"(b[1]));
}

// split two floats into packed bf16x2 hi + lo(residual)
__device__ __forceinline__ void split2(float a, float b, uint32_t& hi, uint32_t& lo) {
    __nv_bfloat162 h = __floats2bfloat162_rn(a, b);
    hi = *(uint32_t*)&h;
    float ra = a - __bfloat162float(h.x);
    float rb = b - __bfloat162float(h.y);
    __nv_bfloat162 l2 = __floats2bfloat162_rn(ra, rb);
    lo = *(uint32_t*)&l2;
}

// ---------------- pre-pass: fp32 -> bf16 hi/lo split --------------------------
__global__ void split_kernel(const float* __restrict__ A,
                             __nv_bfloat16* __restrict__ hi,
                             __nv_bfloat16* __restrict__ lo, int n)
{
    int i = blockIdx.x * 256 + threadIdx.x;
    if (i < n) {
        float v = A[i];
        __nv_bfloat16 h = __float2bfloat16(v);
        hi[i] = h;
        lo[i] = __float2bfloat16(v - __bfloat162float(h));
    }
}

// transpose + split: W [K,N] fp32 -> hi/lo [N,K] bf16
__global__ void tsplit_kernel(const float* __restrict__ W,
                              __nv_bfloat16* __restrict__ hi,
                              __nv_bfloat16* __restrict__ lo, int K, int N)
{
    __shared__ float t[32][33];
    int k0 = blockIdx.y * 32, n0 = blockIdx.x * 32;
    int tx = threadIdx.x, ty = threadIdx.y;   // block (32,8)
#pragma unroll
    for (int i = 0; i < 32; i += 8)
        t[ty + i][tx] = W[(size_t)(k0 + ty + i) * N + n0 + tx];
    __syncthreads();
#pragma unroll
    for (int i = 0; i < 32; i += 8) {
        float v = t[tx][ty + i];
        size_t o = (size_t)(n0 + ty + i) * K + k0 + tx;
        __nv_bfloat16 h = __float2bfloat16(v);
        hi[o] = h;
        lo[o] = __float2bfloat16(v - __bfloat162float(h));
    }
}

// ---------------- mma.sync bf16 split GEMM ------------------------------------
// C[M,N] = A[M,K] @ Bt[N,K]^T + bias, fp32 accum.
// CTA tile 128x128, BK=64, 8 warps (4m x 2n), warp tile 32x64.
// EPIROPE: epilogue applies RoPE + hi/lo split, scattering to g_qh..g_vl.
#define GBM 128
#define GBN 128
#define GBK 64
#define KPAD 72
#define OFF_AH 0
#define OFF_AL (128 * KPAD * 2)          // 18432
#define OFF_BH (2 * 128 * KPAD * 2)      // 36864
#define OFF_BL (3 * 128 * KPAD * 2)      // 55296
#define GSMEM  (4 * 128 * KPAD * 2)      // 73728 B

template <int EPIROPE>
__global__ void __launch_bounds__(256, 2)
gemm_mma_kernel(const __nv_bfloat16* __restrict__ Ahi,
                const __nv_bfloat16* __restrict__ Alo,
                const __nv_bfloat16* __restrict__ Bhi,
                const __nv_bfloat16* __restrict__ Blo,
                const float* __restrict__ bias,
                const float* __restrict__ cosT,
                const float* __restrict__ sinT,
                float* __restrict__ Cm,
                int N, int K)
{
    extern __shared__ __align__(16) unsigned char smem[];
    __nv_bfloat16* sAh = (__nv_bfloat16*)(smem + OFF_AH);
    __nv_bfloat16* sAl = (__nv_bfloat16*)(smem + OFF_AL);
    __nv_bfloat16* sBh = (__nv_bfloat16*)(smem + OFF_BH);
    __nv_bfloat16* sBl = (__nv_bfloat16*)(smem + OFF_BL);
    const uint32_t sb = smem_u32(smem);

    const int tid  = threadIdx.x;
    const int lane = tid & 31;
    const int w    = tid >> 5;
    const int m_base = (w & 3) * 32;    // warp m offset
    const int n_base = (w >> 2) * 64;   // warp n offset

    const int m0 = blockIdx.y * GBM;
    const int n0 = blockIdx.x * GBN;

    float d[2][8][4];
#pragma unroll
    for (int i = 0; i < 2; i++)
#pragma unroll
        for (int j = 0; j < 8; j++)
#pragma unroll
            for (int r = 0; r < 4; r++) d[i][j][r] = 0.f;

    const int a_m   = m_base + (lane & 7) + ((lane >> 3) & 1) * 8;
    const int a_khi = (lane >> 4) * 8;
    const int b_g   = lane >> 3;
    const int b_n8  = (b_g >> 1) * 8 + (lane & 7);
    const int b_k8  = (b_g & 1) * 8;

    for (int k0 = 0; k0 < K; k0 += GBK) {
        // ---- load chunk: A and B 128x64 hi/lo tiles (144B padded rows) ----
#pragma unroll
        for (int it = 0; it < 4; it++) {
            int u = tid + it * 256;          // 0..1023
            int row = u >> 3, c8 = (u & 7) * 8;
            int s = row * KPAD + c8;
            size_t ga = (size_t)(m0 + row) * K + k0 + c8;
            size_t gb = (size_t)(n0 + row) * K + k0 + c8;
            *(uint4*)(sAh + s) = *(const uint4*)(Ahi + ga);
            *(uint4*)(sAl + s) = *(const uint4*)(Alo + ga);
            *(uint4*)(sBh + s) = *(const uint4*)(Bhi + gb);
            *(uint4*)(sBl + s) = *(const uint4*)(Blo + gb);
        }
        __syncthreads();

#pragma unroll
        for (int ks = 0; ks < 4; ks++) {
            const int koff = ks * 16;
            uint32_t ah[2][4], al[2][4];
#pragma unroll
            for (int mf = 0; mf < 2; mf++) {
                uint32_t off = (uint32_t)((a_m + mf * 16) * KPAD + koff + a_khi) * 2;
                ldsm_x4(ah[mf], sb + OFF_AH + off);
                ldsm_x4(al[mf], sb + OFF_AL + off);
            }
#pragma unroll
            for (int pr = 0; pr < 4; pr++) {
                uint32_t off = (uint32_t)((n_base + pr * 16 + b_n8) * KPAD + koff + b_k8) * 2;
                uint32_t rh[4], rl[4];
                ldsm_x4(rh, sb + OFF_BH + off);
                ldsm_x4(rl, sb + OFF_BL + off);
                uint32_t bh0[2] = {rh[0], rh[1]}, bh1[2] = {rh[2], rh[3]};
                uint32_t bl0[2] = {rl[0], rl[1]}, bl1[2] = {rl[2], rl[3]};
#pragma unroll
                for (int mf = 0; mf < 2; mf++) {
                    mma_bf16(d[mf][pr * 2 + 0], ah[mf], bh0);
                    mma_bf16(d[mf][pr * 2 + 0], ah[mf], bl0);
                    mma_bf16(d[mf][pr * 2 + 0], al[mf], bh0);
                    mma_bf16(d[mf][pr * 2 + 1], ah[mf], bh1);
                    mma_bf16(d[mf][pr * 2 + 1], ah[mf], bl1);
                    mma_bf16(d[mf][pr * 2 + 1], al[mf], bh1);
                }
            }
        }
        __syncthreads();
    }

    if (EPIROPE) {
        // 128-col tiles never straddle a q/k/v boundary (1024 % 128 == 0)
        const int sec = n0 >> 10;            // 0=q 1=k 2=v
#pragma unroll
        for (int mf = 0; mf < 2; mf++) {
            int row = m0 + m_base + mf * 16 + (lane >> 2);
#pragma unroll
            for (int rr = 0; rr < 2; rr++) {
                int r = row + rr * 8;
                int t = r & (TT - 1), b = r >> 11;
#pragma unroll
                for (int nf = 0; nf < 8; nf++) {
                    int ncol = n0 + n_base + nf * 8 + 2 * (lane & 3);  // even
                    int h    = (ncol & 1023) >> 6;
                    int dcol = ncol & 63;
                    size_t obase = ((size_t)(b * HH + h) * TT + t) * DD + dcol;
                    float v0 = d[mf][nf][rr * 2 + 0] + bias[ncol];
                    float v1 = d[mf][nf][rr * 2 + 1] + bias[ncol + 1];
                    uint32_t hi, lo;
                    if (sec == 2) {
                        split2(v0, v1, hi, lo);
                        *(uint32_t*)&g_vh[obase] = hi;
                        *(uint32_t*)&g_vl[obase] = lo;
                    } else {
                        int i = dcol >> 1;
                        float c = cosT[t * 32 + i], s = sinT[t * 32 + i];
                        float r0 = v0 * c - v1 * s;
                        float r1 = v0 * s + v1 * c;
                        if (sec == 0) {
                            split2(r0 * 0.125f, r1 * 0.125f, hi, lo);
                            *(uint32_t*)&g_qh[obase] = hi;
                            *(uint32_t*)&g_ql[obase] = lo;
                        } else {
                            split2(r0, r1, hi, lo);
                            *(uint32_t*)&g_kh[obase] = hi;
                            *(uint32_t*)&g_kl[obase] = lo;
                        }
                    }
                }
            }
        }
    } else {
#pragma unroll
        for (int mf = 0; mf < 2; mf++) {
#pragma unroll
            for (int nf = 0; nf < 8; nf++) {
                int row = m0 + m_base + mf * 16 + (lane >> 2);
                int col = n0 + n_base + nf * 8 + 2 * (lane & 3);
                float bx = bias[col], by = bias[col + 1];
                float2 v0 = {d[mf][nf][0] + bx, d[mf][nf][1] + by};
                float2 v1 = {d[mf][nf][2] + bx, d[mf][nf][3] + by};
                *(float2*)&Cm[(size_t)row * N + col]       = v0;
                *(float2*)&Cm[(size_t)(row + 8) * N + col] = v1;
            }
        }
    }
}

// ---------------- tensor-core causal flash attention --------------------------
// BQ=128, BKV=64, 8 warps x 16 q-rows. Q frags register-resident; K/V per chunk.
// __launch_bounds__(256, 2): 2 CTAs/SM so one CTA's softmax overlaps MMAs.
#define FKP 72
#define F_QH 0
#define F_QL 18432
#define F_KH 0
#define F_KL 9216
#define F_VH 18432
#define F_VL 27648
#define FLASH_SMEM 36864

__global__ void __launch_bounds__(256, 2)
flash_mma_kernel(const __nv_bfloat16* __restrict__ Qh,
                 const __nv_bfloat16* __restrict__ Ql,
                 const __nv_bfloat16* __restrict__ Kh,
                 const __nv_bfloat16* __restrict__ Kl,
                 const __nv_bfloat16* __restrict__ Vh,
                 const __nv_bfloat16* __restrict__ Vl)
{
    extern __shared__ __align__(16) unsigned char smem[];
    const uint32_t sb = smem_u32(smem);
    const int tid  = threadIdx.x;
    const int lane = tid & 31;
    const int w    = tid >> 5;

    const int qt = gridDim.x - 1 - blockIdx.x;   // heavy tiles first
    const int q0 = qt * 128;
    const int bh = blockIdx.y;
    const size_t gbase = (size_t)bh * TT * DD;

    // ---- load Q tile (hi/lo) into smem ----
#pragma unroll
    for (int it = 0; it < 4; it++) {
        int u = tid + it * 256;                  // 0..1023
        int row = u >> 3, c8 = (u & 7) * 8;
        size_t g = gbase + (size_t)(q0 + row) * DD + c8;
        int s = row * FKP + c8;
        *(uint4*)(smem + F_QH + s * 2) = *(const uint4*)(Qh + g);
        *(uint4*)(smem + F_QL + s * 2) = *(const uint4*)(Ql + g);
    }
    __syncthreads();

    // ---- Q fragments into registers ----
    const int a_m   = w * 16 + (lane & 7) + ((lane >> 3) & 1) * 8;
    const int a_khi = (lane >> 4) * 8;
    uint32_t qh[4][4], ql[4][4];
#pragma unroll
    for (int ks = 0; ks < 4; ks++) {
        uint32_t off = (uint32_t)(a_m * FKP + ks * 16 + a_khi) * 2;
        ldsm_x4(qh[ks], sb + F_QH + off);
        ldsm_x4(ql[ks], sb + F_QL + off);
    }
    __syncthreads();   // done with Q smem; reuse for K/V

    const int b_g   = lane >> 3;
    const int b_n8  = (b_g >> 1) * 8 + (lane & 7);
    const int b_k8  = (b_g & 1) * 8;
    const int v_r8  = (b_g & 1) * 8 + (lane & 7);
    const int v_c8  = (b_g >> 1) * 8;

    float o[8][4];
#pragma unroll
    for (int nf = 0; nf < 8; nf++)
#pragma unroll
        for (int j = 0; j < 4; j++) o[nf][j] = 0.f;
    float m0 = -1e30f, m1 = -1e30f, l0 = 0.f, l1 = 0.f;

    const int r0g = q0 + w * 16 + (lane >> 2);
    const int nchunk = 2 * qt + 2;

    for (int ch = 0; ch < nchunk; ch++) {
        const int kv0 = ch * 64;
        __syncthreads();   // previous chunk's smem reads done
#pragma unroll
        for (int it = 0; it < 2; it++) {
            int u = tid + it * 256;              // 0..511
            int row = u >> 3, c8 = (u & 7) * 8;
            size_t g = gbase + (size_t)(kv0 + row) * DD + c8;
            int s = (row * FKP + c8) * 2;
            *(uint4*)(smem + F_KH + s) = *(const uint4*)(Kh + g);
            *(uint4*)(smem + F_KL + s) = *(const uint4*)(Kl + g);
            *(uint4*)(smem + F_VH + s) = *(const uint4*)(Vh + g);
            *(uint4*)(smem + F_VL + s) = *(const uint4*)(Vl + g);
        }
        __syncthreads();

        // ---- S = Q K^T (3-term split) ----
        float s4[8][4];
#pragma unroll
        for (int nf = 0; nf < 8; nf++)
#pragma unroll
            for (int j = 0; j < 4; j++) s4[nf][j] = 0.f;

#pragma unroll
        for (int ks = 0; ks < 4; ks++) {
#pragma unroll
            for (int pr = 0; pr < 4; pr++) {
                uint32_t off = (uint32_t)((pr * 16 + b_n8) * FKP + ks * 16 + b_k8) * 2;
                uint32_t kh4[4], kl4[4];
                ldsm_x4(kh4, sb + F_KH + off);
                ldsm_x4(kl4, sb + F_KL + off);
                uint32_t bh0[2] = {kh4[0], kh4[1]}, bh1[2] = {kh4[2], kh4[3]};
                uint32_t bl0[2] = {kl4[0], kl4[1]}, bl1[2] = {kl4[2], kl4[3]};
                mma_bf16(s4[2 * pr], qh[ks], bh0);
                mma_bf16(s4[2 * pr], qh[ks], bl0);
                mma_bf16(s4[2 * pr], ql[ks], bh0);
                mma_bf16(s4[2 * pr + 1], qh[ks], bh1);
                mma_bf16(s4[2 * pr + 1], qh[ks], bl1);
                mma_bf16(s4[2 * pr + 1], ql[ks], bh1);
            }
        }

        // ---- causal mask (only last two chunks of this tile) ----
        if (ch >= 2 * qt) {
#pragma unroll
            for (int nf = 0; nf < 8; nf++) {
                int cbase = kv0 + nf * 8 + (lane & 3) * 2;
#pragma unroll
                for (int j = 0; j < 4; j++) {
                    int col = cbase + (j & 1);
                    int row = r0g + ((j >> 1) << 3);
                    if (col > row) s4[nf][j] = -1e30f;
                }
            }
        }

        // ---- online softmax ----
        float mx0 = -1e30f, mx1 = -1e30f;
#pragma unroll
        for (int nf = 0; nf < 8; nf++) {
            mx0 = fmaxf(mx0, fmaxf(s4[nf][0], s4[nf][1]));
            mx1 = fmaxf(mx1, fmaxf(s4[nf][2], s4[nf][3]));
        }
        mx0 = fmaxf(mx0, __shfl_xor_sync(0xffffffffu, mx0, 1));
        mx0 = fmaxf(mx0, __shfl_xor_sync(0xffffffffu, mx0, 2));
        mx1 = fmaxf(mx1, __shfl_xor_sync(0xffffffffu, mx1, 1));
        mx1 = fmaxf(mx1, __shfl_xor_sync(0xffffffffu, mx1, 2));
        float mn0 = fmaxf(m0, mx0), mn1 = fmaxf(m1, mx1);
        float al0 = __expf(m0 - mn0), al1 = __expf(m1 - mn1);
        float sum0 = 0.f, sum1 = 0.f;
#pragma unroll
        for (int nf = 0; nf < 8; nf++) {
            s4[nf][0] = __expf(s4[nf][0] - mn0);
            s4[nf][1] = __expf(s4[nf][1] - mn0);
            s4[nf][2] = __expf(s4[nf][2] - mn1);
            s4[nf][3] = __expf(s4[nf][3] - mn1);
            sum0 += s4[nf][0] + s4[nf][1];
            sum1 += s4[nf][2] + s4[nf][3];
        }
        sum0 += __shfl_xor_sync(0xffffffffu, sum0, 1);
        sum0 += __shfl_xor_sync(0xffffffffu, sum0, 2);
        sum1 += __shfl_xor_sync(0xffffffffu, sum1, 1);
        sum1 += __shfl_xor_sync(0xffffffffu, sum1, 2);
        l0 = l0 * al0 + sum0;  m0 = mn0;
        l1 = l1 * al1 + sum1;  m1 = mn1;
#pragma unroll
        for (int nf = 0; nf < 8; nf++) {
            o[nf][0] *= al0; o[nf][1] *= al0;
            o[nf][2] *= al1; o[nf][3] *= al1;
        }

        // ---- O += P V (3-term split, P from registers) ----
#pragma unroll
        for (int ks = 0; ks < 4; ks++) {
            uint32_t pa_h[4], pa_l[4];
            split2(s4[2 * ks][0],     s4[2 * ks][1],     pa_h[0], pa_l[0]);
            split2(s4[2 * ks][2],     s4[2 * ks][3],     pa_h[1], pa_l[1]);
            split2(s4[2 * ks + 1][0], s4[2 * ks + 1][1], pa_h[2], pa_l[2]);
            split2(s4[2 * ks + 1][2], s4[2 * ks + 1][3], pa_h[3], pa_l[3]);
#pragma unroll
            for (int pr = 0; pr < 4; pr++) {
                uint32_t off = (uint32_t)((ks * 16 + v_r8) * FKP + pr * 16 + v_c8) * 2;
                uint32_t vh4[4], vl4[4];
                ldsm_x4_t(vh4, sb + F_VH + off);
                ldsm_x4_t(vl4, sb + F_VL + off);
                uint32_t bh0[2] = {vh4[0], vh4[1]}, bh1[2] = {vh4[2], vh4[3]};
                uint32_t bl0[2] = {vl4[0], vl4[1]}, bl1[2] = {vl4[2], vl4[3]};
                mma_bf16(o[2 * pr], pa_h, bh0);
                mma_bf16(o[2 * pr], pa_h, bl0);
                mma_bf16(o[2 * pr], pa_l, bh0);
                mma_bf16(o[2 * pr + 1], pa_h, bh1);
                mma_bf16(o[2 * pr + 1], pa_h, bl1);
                mma_bf16(o[2 * pr + 1], pa_l, bh1);
            }
        }
    }

    // ---- epilogue: O /= l, write bf16 hi/lo to [B,T,C] ----
    float inv0 = 1.f / l0, inv1 = 1.f / l1;
    int b = bh >> 4, h = bh & 15;
    size_t base0 = ((size_t)(b * TT + r0g)) * CC + h * DD;
    size_t base1 = ((size_t)(b * TT + r0g + 8)) * CC + h * DD;
#pragma unroll
    for (int nf = 0; nf < 8; nf++) {
        int c = nf * 8 + (lane & 3) * 2;
        uint32_t hi, lo;
        split2(o[nf][0] * inv0, o[nf][1] * inv0, hi, lo);
        *(uint32_t*)&g_yhi[base0 + c] = hi;
        *(uint32_t*)&g_ylo[base0 + c] = lo;
        split2(o[nf][2] * inv1, o[nf][3] * inv1, hi, lo);
        *(uint32_t*)&g_yhi[base1 + c] = hi;
        *(uint32_t*)&g_ylo[base1 + c] = lo;
    }
}

// ---------------- launcher ----------------------------------------------------
extern "C" void kernel_launch(void* const* d_in, const int* in_sizes, int n_in,
                              void* d_out, int out_size)
{
    const float* x     = (const float*)d_in[0];
    const float* Wqkv  = (const float*)d_in[1];
    const float* bqkv  = (const float*)d_in[2];
    const float* Wproj = (const float*)d_in[3];
    const float* bproj = (const float*)d_in[4];
    const float* cosT  = (const float*)d_in[5];
    const float* sinT  = (const float*)d_in[6];
    float* out = (float*)d_out;

    __nv_bfloat16 *xhi, *xlo, *wqhi, *wqlo, *wphi, *wplo, *yhi, *ylo;
    __nv_bfloat16 *qh, *ql, *kh, *kl, *vh, *vl;
    cudaGetSymbolAddress((void**)&xhi,  g_xhi);
    cudaGetSymbolAddress((void**)&xlo,  g_xlo);
    cudaGetSymbolAddress((void**)&wqhi, g_wqhi);
    cudaGetSymbolAddress((void**)&wqlo, g_wqlo);
    cudaGetSymbolAddress((void**)&wphi, g_wphi);
    cudaGetSymbolAddress((void**)&wplo, g_wplo);
    cudaGetSymbolAddress((void**)&yhi,  g_yhi);
    cudaGetSymbolAddress((void**)&ylo,  g_ylo);
    cudaGetSymbolAddress((void**)&qh,   g_qh);
    cudaGetSymbolAddress((void**)&ql,   g_ql);
    cudaGetSymbolAddress((void**)&kh,   g_kh);
    cudaGetSymbolAddress((void**)&kl,   g_kl);
    cudaGetSymbolAddress((void**)&vh,   g_vh);
    cudaGetSymbolAddress((void**)&vl,   g_vl);

    static bool attr_set = false;
    if (!attr_set) {
        cudaFuncSetAttribute(gemm_mma_kernel<1>,
                             cudaFuncAttributeMaxDynamicSharedMemorySize, GSMEM);
        cudaFuncSetAttribute(gemm_mma_kernel<0>,
                             cudaFuncAttributeMaxDynamicSharedMemorySize, GSMEM);
        cudaFuncSetAttribute(flash_mma_kernel,
                             cudaFuncAttributeMaxDynamicSharedMemorySize, FLASH_SMEM);
        attr_set = true;
    }

    // pre-pass: split x; transpose+split weights
    split_kernel<<<(MM * CC + 255) / 256, 256>>>(x, xhi, xlo, MM * CC);
    tsplit_kernel<<<dim3(C3 / 32, CC / 32), dim3(32, 8)>>>(Wqkv, wqhi, wqlo, CC, C3);
    tsplit_kernel<<<dim3(CC / 32, CC / 32), dim3(32, 8)>>>(Wproj, wphi, wplo, CC, CC);

    // 1) QKV projection, fused bias+RoPE+split epilogue -> g_qh..g_vl
    gemm_mma_kernel<1><<<dim3(C3 / GBN, MM / GBM), 256, GSMEM>>>(
        xhi, xlo, wqhi, wqlo, bqkv, cosT, sinT, nullptr, C3, CC);

    // 2) tensor-core causal flash attention (writes yhi/ylo in [B,T,C])
    flash_mma_kernel<<<dim3(TT / 128, BB * HH), 256, FLASH_SMEM>>>(
        qh, ql, kh, kl, vh, vl);

    // 3) output projection
    gemm_mma_kernel<0><<<dim3(CC / GBN, MM / GBM), 256, GSMEM>>>(
        yhi, ylo, wphi, wplo, bproj, nullptr, nullptr, out, CC, CC);
}